// round 2
// baseline (speedup 1.0000x reference)
#include <cuda_runtime.h>
#include <cstdint>
#include <cstddef>

#define NCN    32      // 2*16 centroid matrices
#define NB     1024    // number of sampled indices
#define NCHUNK 128     // b-chunks in main kernel grid
#define WPB    8       // warps per block (main kernel)
#define QN     6       // Gauss-Legendre nodes for logm

// ---- scratch (static device globals; no allocation APIs) ----
__device__ float g_Cm[NCN * 1024];                    // C^{-1/2}
__device__ float g_Cp[NCN * 1024];                    // C^{+1/2}
__device__ float g_partial[NCHUNK * NCN * 1024];      // per-chunk partial sums of logm

// Gauss-Legendre nodes/weights mapped to [0,1]
__constant__ float c_t[QN] = {0.03376524289842399f, 0.16939530676686774f, 0.38069040695840156f,
                              0.61930959304159844f, 0.83060469323313226f, 0.96623475710157601f};
__constant__ float c_w[QN] = {0.08566224618958517f, 0.18038078652406930f, 0.23395696728634552f,
                              0.23395696728634552f, 0.18038078652406930f, 0.08566224618958517f};

// ============================================================================
// Kernel 1: C^{+1/2}, C^{-1/2} via coupled Newton-Schulz sqrt iteration.
// grid(32), block(1024): thread (i,j) owns one matrix element.
// ============================================================================
__global__ void prep_kernel(const float* __restrict__ C) {
    __shared__ float sA[5][32 * 33];
    __shared__ float s_c;
    const int cn = blockIdx.x, tid = threadIdx.x;
    const int i = tid >> 5, j = tid & 31;
    const float cij = C[cn * 1024 + i * 32 + j];
    if (tid == 0) {
        float s = 0.f;
        #pragma unroll
        for (int k = 0; k < 32; k++) s += C[cn * 1024 + k * 33];
        s_c = s * (1.f / 32.f);
    }
    __syncthreads();
    const float c = s_c, invc = 1.f / c;
    float* Y = sA[0]; float* Z = sA[1]; float* U = sA[2]; float* V = sA[3]; float* P = sA[4];
    Y[i * 33 + j] = cij * invc;
    Z[i * 33 + j] = (i == j) ? 1.f : 0.f;
    __syncthreads();
    for (int it = 0; it < 10; it++) {
        float a = 0.f;
        #pragma unroll
        for (int k = 0; k < 32; k++) a += Z[i * 33 + k] * Y[k * 33 + j];
        P[i * 33 + j] = ((i == j) ? 1.5f : 0.f) - 0.5f * a;
        __syncthreads();
        float a1 = 0.f, a2 = 0.f;
        #pragma unroll
        for (int k = 0; k < 32; k++) {
            a1 += Y[i * 33 + k] * P[k * 33 + j];
            a2 += P[i * 33 + k] * Z[k * 33 + j];
        }
        U[i * 33 + j] = a1;
        V[i * 33 + j] = a2;
        __syncthreads();
        float* t;
        t = Y; Y = U; U = t;
        t = Z; Z = V; V = t;
    }
    const float sc = sqrtf(c), isc = rsqrtf(c);
    g_Cp[cn * 1024 + i * 32 + j] = Y[i * 33 + j] * sc;
    g_Cm[cn * 1024 + i * 32 + j] = Z[i * 33 + j] * isc;
}

// ============================================================================
// Kernel 2: per-sample logm via 6-node quadrature. One warp per (b, cn) task.
// Rows live in registers; Gauss-Jordan inverse with shared-memory pivot-row
// broadcast. Block = 8 warps for one cn, deterministic block-level reduction
// into g_partial.
// ============================================================================
__global__ void __launch_bounds__(256, 2) main_kernel(const float* __restrict__ X,
                                                      const int* __restrict__ idx) {
    __shared__ __align__(16) float sCm[32 * 36];        // stride 36 (16B-aligned rows)
    __shared__ __align__(16) float sBuf[WPB][32 * 36];  // per-warp scratch matrix
    __shared__ __align__(16) float sBc[WPB][32];        // per-warp pivot-row broadcast
    const int tid = threadIdx.x, warp = tid >> 5, lane = tid & 31;
    const int cn = blockIdx.y;
    const int b = blockIdx.x * WPB + warp;

    for (int k = tid; k < 1024; k += 256)
        sCm[(k >> 5) * 36 + (k & 31)] = g_Cm[cn * 1024 + k];
    __syncthreads();

    const int xb = idx[b];
    const float* Xrow = X + (((size_t)xb * NCN + cn) << 10) + (lane << 5);
    float x[32];
    #pragma unroll
    for (int q = 0; q < 8; q++) {
        float4 v = ((const float4*)Xrow)[q];
        x[4 * q] = v.x; x[4 * q + 1] = v.y; x[4 * q + 2] = v.z; x[4 * q + 3] = v.w;
    }

    // W = X * Cm (thread owns row `lane`)
    float wv[32];
    #pragma unroll
    for (int j = 0; j < 32; j++) wv[j] = 0.f;
    #pragma unroll
    for (int k = 0; k < 32; k++) {
        const float xv = x[k];
        #pragma unroll
        for (int q = 0; q < 8; q++) {
            float4 v = ((const float4*)(sCm + k * 36))[q];
            wv[4 * q]     = fmaf(xv, v.x, wv[4 * q]);
            wv[4 * q + 1] = fmaf(xv, v.y, wv[4 * q + 1]);
            wv[4 * q + 2] = fmaf(xv, v.z, wv[4 * q + 2]);
            wv[4 * q + 3] = fmaf(xv, v.w, wv[4 * q + 3]);
        }
    }
    #pragma unroll
    for (int q = 0; q < 8; q++)
        ((float4*)(sBuf[warp] + lane * 36))[q] =
            make_float4(wv[4 * q], wv[4 * q + 1], wv[4 * q + 2], wv[4 * q + 3]);
    __syncwarp();

    // M = Cm * W  (Cm symmetric: M[lane][j] = sum_k Cm[k][lane] * W[k][j])
    float m[32];
    #pragma unroll
    for (int j = 0; j < 32; j++) m[j] = 0.f;
    #pragma unroll
    for (int k = 0; k < 32; k++) {
        const float cv = sCm[k * 36 + lane];
        #pragma unroll
        for (int q = 0; q < 8; q++) {
            float4 v = ((const float4*)(sBuf[warp] + k * 36))[q];
            m[4 * q]     = fmaf(cv, v.x, m[4 * q]);
            m[4 * q + 1] = fmaf(cv, v.y, m[4 * q + 1]);
            m[4 * q + 2] = fmaf(cv, v.z, m[4 * q + 2]);
            m[4 * q + 3] = fmaf(cv, v.w, m[4 * q + 3]);
        }
    }

    // logm(M) ~= sum_i (w_i/t_i) (I - (t_i M + (1-t_i) I)^{-1})
    float acc[32];
    #pragma unroll
    for (int j = 0; j < 32; j++) acc[j] = 0.f;
    float Ssum = 0.f;
    float* bc = sBc[warp];

    #pragma unroll 1
    for (int nd = 0; nd < QN; nd++) {
        const float t = c_t[nd], wq = c_w[nd];
        const float wot = __fdividef(wq, t);
        Ssum += wot;
        float B[32];
        #pragma unroll
        for (int j = 0; j < 32; j++) B[j] = t * m[j];
        #pragma unroll
        for (int j = 0; j < 32; j++)
            if (lane == j) B[j] += (1.f - t);

        // in-place pivot-free Gauss-Jordan inverse (B is SPD, well conditioned)
        #pragma unroll
        for (int k = 0; k < 32; k++) {
            if (lane == k) {
                #pragma unroll
                for (int q = 0; q < 8; q++)
                    ((float4*)bc)[q] =
                        make_float4(B[4 * q], B[4 * q + 1], B[4 * q + 2], B[4 * q + 3]);
            }
            __syncwarp();
            float4 pvv = ((const float4*)bc)[k >> 2];
            const int kk = k & 3;
            const float piv = (kk == 0) ? pvv.x : (kk == 1) ? pvv.y : (kk == 2) ? pvv.z : pvv.w;
            const float ip = __fdividef(1.f, piv);
            // owner lane uses f = piv - 1 so the unified update scales its own row by ip
            const float f = B[k] - ((lane == k) ? 1.f : 0.f);
            const float fp = f * ip;
            #pragma unroll
            for (int q = 0; q < 8; q++) {
                float4 v = ((const float4*)bc)[q];
                B[4 * q]     = fmaf(-fp, v.x, B[4 * q]);
                B[4 * q + 1] = fmaf(-fp, v.y, B[4 * q + 1]);
                B[4 * q + 2] = fmaf(-fp, v.z, B[4 * q + 2]);
                B[4 * q + 3] = fmaf(-fp, v.w, B[4 * q + 3]);
            }
            B[k] = (lane == k) ? ip : -fp;
            __syncwarp();
        }
        #pragma unroll
        for (int j = 0; j < 32; j++) acc[j] = fmaf(-wot, B[j], acc[j]);
    }
    #pragma unroll
    for (int j = 0; j < 32; j++)
        if (lane == j) acc[j] += Ssum;   // the +S*I diagonal term

    __syncwarp();
    #pragma unroll
    for (int q = 0; q < 8; q++)
        ((float4*)(sBuf[warp] + lane * 36))[q] =
            make_float4(acc[4 * q], acc[4 * q + 1], acc[4 * q + 2], acc[4 * q + 3]);
    __syncthreads();

    // deterministic block reduction over the 8 warps -> partial buffer
    float* outp = g_partial + ((size_t)blockIdx.x * NCN + cn) * 1024;
    for (int e = tid; e < 1024; e += 256) {
        const int r = e >> 5, cc = e & 31;
        float s = 0.f;
        #pragma unroll
        for (int wp = 0; wp < WPB; wp++) s += sBuf[wp][r * 36 + cc];
        outp[e] = s;
    }
}

// ============================================================================
// Kernel 3: deterministic chunk reduction, L_m = mean*ETA, then Jacobi
// eigendecomposition of L_m and E = Q diag(sign(l)*exp(|l|)) Q^T  (this is
// what the reference's SVD-based "expm" actually computes for symmetric
// indefinite input), then C_new = C^{1/2} E C^{1/2}.
// grid(32), block(256).
// ============================================================================
__global__ void final_kernel(float* __restrict__ out) {
    __shared__ float sA[32 * 33];   // L_m -> diagonalized
    __shared__ float sQ[32 * 33];   // eigenvectors (columns)
    __shared__ float sCp[32 * 33];
    __shared__ float sE[32 * 33];
    __shared__ float sU[32 * 33];
    __shared__ float gl[32];
    __shared__ float rc[16], rs[16];
    __shared__ int   rp[16], rq[16];
    const int cn = blockIdx.x, tid = threadIdx.x;

    for (int e = tid; e < 1024; e += 256) {
        float s = 0.f;
        const float* pp = g_partial + cn * 1024 + e;
        for (int c = 0; c < NCHUNK; c++) s += pp[(size_t)c * NCN * 1024];
        const int i = e >> 5, j = e & 31;
        sA[i * 33 + j] = s * (0.01f / 1024.f);   // ETA / NB
        sQ[i * 33 + j] = (i == j) ? 1.f : 0.f;
        sCp[i * 33 + j] = g_Cp[cn * 1024 + e];
    }
    __syncthreads();

    // Two-sided parallel Jacobi: 10 sweeps x 31 rounds x 16 disjoint pairs.
    for (int sweep = 0; sweep < 10; sweep++) {
        for (int r = 0; r < 31; r++) {
            if (tid < 16) {
                int p, q;
                if (tid == 0) { p = 31; q = r; }
                else { p = (r + tid) % 31; q = (r - tid + 31) % 31; }
                const float app = sA[p * 33 + p];
                const float aqq = sA[q * 33 + q];
                const float apq = sA[p * 33 + q];
                float cc = 1.f, ss = 0.f;
                if (apq != 0.f) {
                    const float theta = (aqq - app) / (2.f * apq);
                    const float tt = copysignf(1.f, theta) /
                                     (fabsf(theta) + sqrtf(theta * theta + 1.f));
                    cc = rsqrtf(tt * tt + 1.f);
                    ss = tt * cc;
                }
                rp[tid] = p; rq[tid] = q; rc[tid] = cc; rs[tid] = ss;
            }
            __syncthreads();
            // Column rotations on A and Q (A <- A J, Q <- Q J). Disjoint writes.
            for (int task = tid; task < 512; task += 256) {
                const int pr = task >> 5, row = task & 31;
                const int p = rp[pr], q = rq[pr];
                const float cc = rc[pr], ss = rs[pr];
                const float ap = sA[row * 33 + p], aq = sA[row * 33 + q];
                sA[row * 33 + p] = cc * ap - ss * aq;
                sA[row * 33 + q] = ss * ap + cc * aq;
                const float qp = sQ[row * 33 + p], qq = sQ[row * 33 + q];
                sQ[row * 33 + p] = cc * qp - ss * qq;
                sQ[row * 33 + q] = ss * qp + cc * qq;
            }
            __syncthreads();
            // Row rotations on A (A <- J^T A). Disjoint writes.
            for (int task = tid; task < 512; task += 256) {
                const int pr = task >> 5, col = task & 31;
                const int p = rp[pr], q = rq[pr];
                const float cc = rc[pr], ss = rs[pr];
                const float ap = sA[p * 33 + col], aq = sA[q * 33 + col];
                sA[p * 33 + col] = cc * ap - ss * aq;
                sA[q * 33 + col] = ss * ap + cc * aq;
            }
            __syncthreads();
        }
    }

    // g(lambda) = sign(lambda) * exp(|lambda|)   (matches SVD-based "expm")
    if (tid < 32) {
        const float lam = sA[tid * 33 + tid];
        gl[tid] = copysignf(expf(fabsf(lam)), lam);
    }
    __syncthreads();

    // E = Q diag(gl) Q^T
    for (int e = tid; e < 1024; e += 256) {
        const int i = e >> 5, j = e & 31;
        float s = 0.f;
        #pragma unroll
        for (int k = 0; k < 32; k++)
            s = fmaf(sQ[i * 33 + k] * gl[k], sQ[j * 33 + k], s);
        sE[i * 33 + j] = s;
    }
    __syncthreads();

    // U = E * Cp
    for (int e = tid; e < 1024; e += 256) {
        const int i = e >> 5, j = e & 31;
        float s = 0.f;
        #pragma unroll
        for (int k = 0; k < 32; k++)
            s = fmaf(sE[i * 33 + k], sCp[k * 33 + j], s);
        sU[i * 33 + j] = s;
    }
    __syncthreads();

    // C_new = Cp * U
    for (int e = tid; e < 1024; e += 256) {
        const int i = e >> 5, j = e & 31;
        float s = 0.f;
        #pragma unroll
        for (int k = 0; k < 32; k++)
            s = fmaf(sCp[i * 33 + k], sU[k * 33 + j], s);
        out[cn * 1024 + e] = s;
    }
}

// ============================================================================
extern "C" void kernel_launch(void* const* d_in, const int* in_sizes, int n_in,
                              void* d_out, int out_size) {
    const float* X = nullptr;
    const float* C = nullptr;
    const int* idx = nullptr;
    for (int i = 0; i < n_in; i++) {
        if (in_sizes[i] == NB) idx = (const int*)d_in[i];
        else if (in_sizes[i] == NCN * 1024) C = (const float*)d_in[i];
        else X = (const float*)d_in[i];
    }

    prep_kernel<<<NCN, 1024>>>(C);
    dim3 grid(NCHUNK, NCN);
    main_kernel<<<grid, 256>>>(X, idx);
    final_kernel<<<NCN, 256>>>((float*)d_out);
}

// round 3
// speedup vs baseline: 1.8338x; 1.8338x over previous
#include <cuda_runtime.h>
#include <cstdint>
#include <cstddef>

#define NCN    32      // 2*16 centroid matrices
#define NB     1024    // number of sampled indices
#define NBINS  2048    // batch size B (histogram bins)
#define NCHUNK 128     // b-chunks in main kernel grid
#define WPB    8       // warps per block (main kernel)
#define QN     3       // Gauss-Legendre nodes for logm
#define SSUM   3.6666666666666667f   // sum of w_i/t_i for QN=3

// ---- scratch (static device globals; no allocation APIs) ----
__device__ float g_Cm[NCN * 1024];                    // C^{-1/2}
__device__ float g_Cp[NCN * 1024];                    // C^{+1/2}
__device__ float g_partial[NCHUNK * NCN * 1024];      // per-chunk partial sums of logm
__device__ int   g_hist[NBINS];
__device__ int   g_list[NB];                          // distinct xb values (ascending)
__device__ float g_cnt[NB];                           // multiplicity weights (0 = idle slot)

// Gauss-Legendre 3-node on [0,1]
__constant__ float c_t[QN]   = {0.1127016653792583f, 0.5f, 0.8872983346207417f};
__constant__ float c_wot[QN] = {2.4647175961687270f, 0.8888888888888889f, 0.3130601816090510f};

// ---- packed f32x2 helpers ----
union f2u { float2 f; unsigned long long u; };
__device__ __forceinline__ float2 ffma2(float2 a, float2 b, float2 c) {
    f2u A, B, C, R; A.f = a; B.f = b; C.f = c;
    asm("fma.rn.f32x2 %0, %1, %2, %3;" : "=l"(R.u) : "l"(A.u), "l"(B.u), "l"(C.u));
    return R.f;
}
struct __align__(16) pf4 { float2 lo, hi; };

__device__ __forceinline__ float f4c(const float4 v, int c) {
    return c == 0 ? v.x : c == 1 ? v.y : c == 2 ? v.z : v.w;
}

// ============================================================================
// Dedup: histogram + ordered compaction (all integer => deterministic)
// ============================================================================
__global__ void hist_zero_kernel() {
    g_hist[blockIdx.x * 1024 + threadIdx.x] = 0;
}
__global__ void hist_kernel(const int* __restrict__ idx) {
    atomicAdd(&g_hist[idx[threadIdx.x]], 1);
}
__global__ void compact_kernel() {
    __shared__ int s1[1024], s2[1024];
    const int t = threadIdx.x;
    const int h0 = g_hist[2 * t], h1 = g_hist[2 * t + 1];
    const int p0 = h0 > 0, p1 = h1 > 0;
    s1[t] = p0 + p1;
    g_list[t] = 0; g_cnt[t] = 0.f;   // zero all task slots
    __syncthreads();
    int* src = s1; int* dst = s2;
    for (int off = 1; off < 1024; off <<= 1) {
        int v = src[t];
        if (t >= off) v += src[t - off];
        dst[t] = v;
        __syncthreads();
        int* tmp = src; src = dst; dst = tmp;
    }
    const int excl = src[t] - (p0 + p1);
    if (p0) { g_list[excl] = 2 * t;      g_cnt[excl] = (float)h0; }
    if (p1) { g_list[excl + p0] = 2 * t + 1; g_cnt[excl + p0] = (float)h1; }
}
// fallback when batch != NBINS: no dedup, weight 1
__global__ void nodedup_kernel(const int* __restrict__ idx) {
    g_list[threadIdx.x] = idx[threadIdx.x];
    g_cnt[threadIdx.x] = 1.f;
}

// ============================================================================
// Kernel 1: C^{+1/2}, C^{-1/2} via coupled Newton-Schulz sqrt iteration.
// ============================================================================
__global__ void prep_kernel(const float* __restrict__ C) {
    __shared__ float sA[5][32 * 33];
    __shared__ float s_c;
    const int cn = blockIdx.x, tid = threadIdx.x;
    const int i = tid >> 5, j = tid & 31;
    const float cij = C[cn * 1024 + i * 32 + j];
    if (tid == 0) {
        float s = 0.f;
        #pragma unroll
        for (int k = 0; k < 32; k++) s += C[cn * 1024 + k * 33];
        s_c = s * (1.f / 32.f);
    }
    __syncthreads();
    const float c = s_c, invc = 1.f / c;
    float* Y = sA[0]; float* Z = sA[1]; float* U = sA[2]; float* V = sA[3]; float* P = sA[4];
    Y[i * 33 + j] = cij * invc;
    Z[i * 33 + j] = (i == j) ? 1.f : 0.f;
    __syncthreads();
    for (int it = 0; it < 6; it++) {
        float a = 0.f;
        #pragma unroll
        for (int k = 0; k < 32; k++) a += Z[i * 33 + k] * Y[k * 33 + j];
        P[i * 33 + j] = ((i == j) ? 1.5f : 0.f) - 0.5f * a;
        __syncthreads();
        float a1 = 0.f, a2 = 0.f;
        #pragma unroll
        for (int k = 0; k < 32; k++) {
            a1 += Y[i * 33 + k] * P[k * 33 + j];
            a2 += P[i * 33 + k] * Z[k * 33 + j];
        }
        U[i * 33 + j] = a1;
        V[i * 33 + j] = a2;
        __syncthreads();
        float* t;
        t = Y; Y = U; U = t;
        t = Z; Z = V; V = t;
    }
    const float sc = sqrtf(c), isc = rsqrtf(c);
    g_Cp[cn * 1024 + i * 32 + j] = Y[i * 33 + j] * sc;
    g_Cm[cn * 1024 + i * 32 + j] = Z[i * 33 + j] * isc;
}

// ============================================================================
// Kernel 2: weighted per-distinct-sample logm via 3-node quadrature.
// One warp per (slot, cn). Packed f32x2 math, double-buffered pivot bcast.
// ============================================================================
__global__ void __launch_bounds__(256, 2) main_kernel(const float* __restrict__ X) {
    __shared__ __align__(16) float sCm[32 * 36];        // stride 36 (16B-aligned rows)
    __shared__ __align__(16) float sBuf[WPB][32 * 36];  // per-warp matrix (row = lane)
    __shared__ __align__(16) float sBc[WPB][2][32];     // double-buffered pivot row
    const int tid = threadIdx.x, warp = tid >> 5, lane = tid & 31;
    const int cn = blockIdx.y;
    const int slot = blockIdx.x * WPB + warp;

    for (int k = tid; k < 1024; k += 256)
        sCm[(k >> 5) * 36 + (k & 31)] = g_Cm[cn * 1024 + k];
    __syncthreads();

    float* bufrow = sBuf[warp] + lane * 36;
    pf4* br = (pf4*)bufrow;
    const float w = g_cnt[slot];

    if (w > 0.f) {
        const int xb = g_list[slot];
        const float* Xrow = X + (((size_t)xb * NCN + cn) << 10) + (lane << 5);
        float4 x4[8];
        #pragma unroll
        for (int q = 0; q < 8; q++) x4[q] = ((const float4*)Xrow)[q];

        // W = X * Cm (lane owns row `lane`)
        float2 wv[16];
        #pragma unroll
        for (int q = 0; q < 16; q++) wv[q] = make_float2(0.f, 0.f);
        #pragma unroll
        for (int k = 0; k < 32; k++) {
            const float xv = f4c(x4[k >> 2], k & 3);
            const float2 xv2 = make_float2(xv, xv);
            const pf4* cr = (const pf4*)(sCm + k * 36);
            #pragma unroll
            for (int q = 0; q < 8; q++) {
                pf4 v = cr[q];
                wv[2 * q]     = ffma2(xv2, v.lo, wv[2 * q]);
                wv[2 * q + 1] = ffma2(xv2, v.hi, wv[2 * q + 1]);
            }
        }
        #pragma unroll
        for (int q = 0; q < 8; q++) {
            pf4 v; v.lo = wv[2 * q]; v.hi = wv[2 * q + 1];
            br[q] = v;
        }
        __syncwarp();

        // M = Cm * W (Cm symmetric: M[lane][j] = sum_k Cm[k][lane] * W[k][j])
        float2 m2[16];
        #pragma unroll
        for (int q = 0; q < 16; q++) m2[q] = make_float2(0.f, 0.f);
        #pragma unroll
        for (int k = 0; k < 32; k++) {
            const float cv = sCm[k * 36 + lane];
            const float2 cv2 = make_float2(cv, cv);
            const pf4* wr = (const pf4*)(sBuf[warp] + k * 36);
            #pragma unroll
            for (int q = 0; q < 8; q++) {
                pf4 v = wr[q];
                m2[2 * q]     = ffma2(cv2, v.lo, m2[2 * q]);
                m2[2 * q + 1] = ffma2(cv2, v.hi, m2[2 * q + 1]);
            }
        }
        __syncwarp();

        // logm(M) = SSUM*I - sum_nd wot_nd * (t_nd*M + (1-t_nd)*I)^{-1}
        #pragma unroll 1
        for (int nd = 0; nd < QN; nd++) {
            const float t = c_t[nd], wot = c_wot[nd];
            const float omt = 1.f - t;
            float2 B2[16];
            #pragma unroll
            for (int q = 0; q < 16; q++)
                B2[q] = make_float2(t * m2[q].x, t * m2[q].y);
            #pragma unroll
            for (int j = 0; j < 32; j++) {
                if (lane == j) {
                    if (j & 1) B2[j >> 1].y += omt; else B2[j >> 1].x += omt;
                }
            }

            // pivot-free Gauss-Jordan inverse (SPD, well conditioned)
            #pragma unroll
            for (int k = 0; k < 32; k++) {
                float* bc = sBc[warp][k & 1];
                if (lane == k) {
                    pf4* bp = (pf4*)bc;
                    #pragma unroll
                    for (int q = 0; q < 8; q++) {
                        pf4 v; v.lo = B2[2 * q]; v.hi = B2[2 * q + 1];
                        bp[q] = v;
                    }
                }
                __syncwarp();
                pf4 bv[8];
                const pf4* bp = (const pf4*)bc;
                #pragma unroll
                for (int q = 0; q < 8; q++) bv[q] = bp[q];
                const float piv = ((k >> 1) & 1)
                    ? ((k & 1) ? bv[k >> 2].hi.y : bv[k >> 2].hi.x)
                    : ((k & 1) ? bv[k >> 2].lo.y : bv[k >> 2].lo.x);
                const float ip = __fdividef(1.f, piv);
                const float bk = (k & 1) ? B2[k >> 1].y : B2[k >> 1].x;
                const float f = bk - ((lane == k) ? 1.f : 0.f);
                const float fp = f * ip;
                const float2 nfp2 = make_float2(-fp, -fp);
                #pragma unroll
                for (int q = 0; q < 8; q++) {
                    B2[2 * q]     = ffma2(nfp2, bv[q].lo, B2[2 * q]);
                    B2[2 * q + 1] = ffma2(nfp2, bv[q].hi, B2[2 * q + 1]);
                }
                const float nv = (lane == k) ? ip : -fp;
                if (k & 1) B2[k >> 1].y = nv; else B2[k >> 1].x = nv;
            }
            __syncwarp();

            // accumulate -wot * Binv into own sBuf row
            const float2 nwot2 = make_float2(-wot, -wot);
            const float2 zero2 = make_float2(0.f, 0.f);
            if (nd == 0) {
                #pragma unroll
                for (int q = 0; q < 8; q++) {
                    pf4 v;
                    v.lo = ffma2(nwot2, B2[2 * q], zero2);
                    v.hi = ffma2(nwot2, B2[2 * q + 1], zero2);
                    br[q] = v;
                }
            } else {
                #pragma unroll
                for (int q = 0; q < 8; q++) {
                    pf4 v = br[q];
                    v.lo = ffma2(nwot2, B2[2 * q], v.lo);
                    v.hi = ffma2(nwot2, B2[2 * q + 1], v.hi);
                    br[q] = v;
                }
            }
        }

        // scale row by weight and add w*SSUM on the diagonal
        const float2 w2 = make_float2(w, w);
        const float2 zero2 = make_float2(0.f, 0.f);
        #pragma unroll
        for (int q = 0; q < 8; q++) {
            pf4 v = br[q];
            v.lo = ffma2(w2, v.lo, zero2);
            v.hi = ffma2(w2, v.hi, zero2);
            br[q] = v;
        }
        bufrow[lane] += w * SSUM;
    } else {
        pf4 z; z.lo = make_float2(0.f, 0.f); z.hi = z.lo;
        #pragma unroll
        for (int q = 0; q < 8; q++) br[q] = z;
    }
    __syncthreads();

    // deterministic block reduction over the 8 warps -> partial buffer
    float* outp = g_partial + ((size_t)blockIdx.x * NCN + cn) * 1024;
    for (int e = tid; e < 1024; e += 256) {
        const int r = e >> 5, cc = e & 31;
        float s = 0.f;
        #pragma unroll
        for (int wp = 0; wp < WPB; wp++) s += sBuf[wp][r * 36 + cc];
        outp[e] = s;
    }
}

// ============================================================================
// Kernel 3: chunk reduction, L_m = mean*ETA, Jacobi eigendecomp,
// E = Q diag(sign(l)*exp(|l|)) Q^T (matches the SVD-based "expm"),
// C_new = C^{1/2} E C^{1/2}.  grid(32), block(256).
// ============================================================================
__global__ void final_kernel(float* __restrict__ out) {
    __shared__ float sA[32 * 33];
    __shared__ float sQ[32 * 33];
    __shared__ float sCp[32 * 33];
    __shared__ float sE[32 * 33];
    __shared__ float sU[32 * 33];
    __shared__ float gl[32];
    __shared__ float rc[16], rs[16];
    __shared__ int   rp[16], rq[16];
    const int cn = blockIdx.x, tid = threadIdx.x;

    for (int e = tid; e < 1024; e += 256) {
        float s = 0.f;
        const float* pp = g_partial + cn * 1024 + e;
        for (int c = 0; c < NCHUNK; c++) s += pp[(size_t)c * NCN * 1024];
        const int i = e >> 5, j = e & 31;
        sA[i * 33 + j] = s * (0.01f / 1024.f);   // ETA / NB
        sQ[i * 33 + j] = (i == j) ? 1.f : 0.f;
        sCp[i * 33 + j] = g_Cp[cn * 1024 + e];
    }
    __syncthreads();

    for (int sweep = 0; sweep < 8; sweep++) {
        for (int r = 0; r < 31; r++) {
            if (tid < 16) {
                int p, q;
                if (tid == 0) { p = 31; q = r; }
                else { p = (r + tid) % 31; q = (r - tid + 31) % 31; }
                const float app = sA[p * 33 + p];
                const float aqq = sA[q * 33 + q];
                const float apq = sA[p * 33 + q];
                float cc = 1.f, ss = 0.f;
                if (apq != 0.f) {
                    const float theta = (aqq - app) / (2.f * apq);
                    const float tt = copysignf(1.f, theta) /
                                     (fabsf(theta) + sqrtf(theta * theta + 1.f));
                    cc = rsqrtf(tt * tt + 1.f);
                    ss = tt * cc;
                }
                rp[tid] = p; rq[tid] = q; rc[tid] = cc; rs[tid] = ss;
            }
            __syncthreads();
            for (int task = tid; task < 512; task += 256) {
                const int pr = task >> 5, row = task & 31;
                const int p = rp[pr], q = rq[pr];
                const float cc = rc[pr], ss = rs[pr];
                const float ap = sA[row * 33 + p], aq = sA[row * 33 + q];
                sA[row * 33 + p] = cc * ap - ss * aq;
                sA[row * 33 + q] = ss * ap + cc * aq;
                const float qp = sQ[row * 33 + p], qq = sQ[row * 33 + q];
                sQ[row * 33 + p] = cc * qp - ss * qq;
                sQ[row * 33 + q] = ss * qp + cc * qq;
            }
            __syncthreads();
            for (int task = tid; task < 512; task += 256) {
                const int pr = task >> 5, col = task & 31;
                const int p = rp[pr], q = rq[pr];
                const float cc = rc[pr], ss = rs[pr];
                const float ap = sA[p * 33 + col], aq = sA[q * 33 + col];
                sA[p * 33 + col] = cc * ap - ss * aq;
                sA[q * 33 + col] = ss * ap + cc * aq;
            }
            __syncthreads();
        }
    }

    if (tid < 32) {
        const float lam = sA[tid * 33 + tid];
        gl[tid] = copysignf(expf(fabsf(lam)), lam);
    }
    __syncthreads();

    for (int e = tid; e < 1024; e += 256) {
        const int i = e >> 5, j = e & 31;
        float s = 0.f;
        #pragma unroll
        for (int k = 0; k < 32; k++)
            s = fmaf(sQ[i * 33 + k] * gl[k], sQ[j * 33 + k], s);
        sE[i * 33 + j] = s;
    }
    __syncthreads();

    for (int e = tid; e < 1024; e += 256) {
        const int i = e >> 5, j = e & 31;
        float s = 0.f;
        #pragma unroll
        for (int k = 0; k < 32; k++)
            s = fmaf(sE[i * 33 + k], sCp[k * 33 + j], s);
        sU[i * 33 + j] = s;
    }
    __syncthreads();

    for (int e = tid; e < 1024; e += 256) {
        const int i = e >> 5, j = e & 31;
        float s = 0.f;
        #pragma unroll
        for (int k = 0; k < 32; k++)
            s = fmaf(sCp[i * 33 + k], sU[k * 33 + j], s);
        out[cn * 1024 + e] = s;
    }
}

// ============================================================================
extern "C" void kernel_launch(void* const* d_in, const int* in_sizes, int n_in,
                              void* d_out, int out_size) {
    const float* X = nullptr;
    const float* C = nullptr;
    const int* idx = nullptr;
    int xElems = 0;
    for (int i = 0; i < n_in; i++) {
        if (in_sizes[i] == NB) idx = (const int*)d_in[i];
        else if (in_sizes[i] == NCN * 1024) C = (const float*)d_in[i];
        else { X = (const float*)d_in[i]; xElems = in_sizes[i]; }
    }
    const int batch = xElems / (NCN * 1024);

    if (batch == NBINS) {
        hist_zero_kernel<<<NBINS / 1024, 1024>>>();
        hist_kernel<<<1, NB>>>(idx);
        compact_kernel<<<1, 1024>>>();
    } else {
        nodedup_kernel<<<1, NB>>>(idx);
    }
    prep_kernel<<<NCN, 1024>>>(C);
    dim3 grid(NCHUNK, NCN);
    main_kernel<<<grid, 256>>>(X);
    final_kernel<<<NCN, 256>>>((float*)d_out);
}

// round 4
// speedup vs baseline: 2.2671x; 1.2363x over previous
#include <cuda_runtime.h>
#include <cstdint>
#include <cstddef>

#define NCN    32      // 2*16 centroid matrices
#define NB     1024    // number of sampled indices
#define NBINS  2048    // batch size B (histogram bins)
#define NCHUNK 128     // b-chunks in main kernel grid
#define WPB    8       // warps per block (main kernel)
#define QN     2       // Gauss-Legendre nodes for logm
#define SSUM   3.0f    // sum of w_i/t_i for GL-2 on [0,1] (exactly 3)

// ---- scratch (static device globals; no allocation APIs) ----
__device__ float g_Cm[NCN * 1024];                    // C^{-1/2}
__device__ float g_Cp[NCN * 1024];                    // C^{+1/2}
__device__ float g_partial[NCHUNK * NCN * 1024];      // per-chunk partial sums of logm
__device__ int   g_list[NB];                          // distinct xb values (ascending)
__device__ float g_cnt[NB];                           // multiplicity weights (0 = idle slot)

// Gauss-Legendre 2-node on [0,1]
__constant__ float c_t[QN]   = {0.21132486540518713f, 0.78867513459481287f};
__constant__ float c_wot[QN] = {2.3660254037844384f, 0.6339745962155614f};

// ---- packed f32x2 helpers ----
union f2u { float2 f; unsigned long long u; };
__device__ __forceinline__ float2 ffma2(float2 a, float2 b, float2 c) {
    f2u A, B, C, R; A.f = a; B.f = b; C.f = c;
    asm("fma.rn.f32x2 %0, %1, %2, %3;" : "=l"(R.u) : "l"(A.u), "l"(B.u), "l"(C.u));
    return R.f;
}
struct __align__(16) pf4 { float2 lo, hi; };

__device__ __forceinline__ float f4c(const float4 v, int c) {
    return c == 0 ? v.x : c == 1 ? v.y : c == 2 ? v.z : v.w;
}

// ============================================================================
// Dedup in one launch: smem histogram + ordered compaction (deterministic).
// ============================================================================
__global__ void dedup_kernel(const int* __restrict__ idx) {
    __shared__ int h[NBINS];
    __shared__ int s1[1024], s2[1024];
    const int t = threadIdx.x;
    h[t] = 0; h[t + 1024] = 0;
    g_list[t] = 0; g_cnt[t] = 0.f;
    __syncthreads();
    atomicAdd(&h[idx[t]], 1);
    __syncthreads();
    const int h0 = h[2 * t], h1 = h[2 * t + 1];
    const int p0 = h0 > 0, p1 = h1 > 0;
    s1[t] = p0 + p1;
    __syncthreads();
    int* src = s1; int* dst = s2;
    for (int off = 1; off < 1024; off <<= 1) {
        int v = src[t];
        if (t >= off) v += src[t - off];
        dst[t] = v;
        __syncthreads();
        int* tmp = src; src = dst; dst = tmp;
    }
    const int excl = src[t] - (p0 + p1);
    if (p0) { g_list[excl] = 2 * t;          g_cnt[excl] = (float)h0; }
    if (p1) { g_list[excl + p0] = 2 * t + 1; g_cnt[excl + p0] = (float)h1; }
}
// fallback when batch != NBINS: no dedup, weight 1
__global__ void nodedup_kernel(const int* __restrict__ idx) {
    g_list[threadIdx.x] = idx[threadIdx.x];
    g_cnt[threadIdx.x] = 1.f;
}

// ============================================================================
// Kernel 1: C^{+1/2}, C^{-1/2} via coupled Newton-Schulz sqrt iteration.
// ============================================================================
__global__ void prep_kernel(const float* __restrict__ C) {
    __shared__ float sA[5][32 * 33];
    __shared__ float s_c;
    const int cn = blockIdx.x, tid = threadIdx.x;
    const int i = tid >> 5, j = tid & 31;
    const float cij = C[cn * 1024 + i * 32 + j];
    if (tid == 0) {
        float s = 0.f;
        #pragma unroll
        for (int k = 0; k < 32; k++) s += C[cn * 1024 + k * 33];
        s_c = s * (1.f / 32.f);
    }
    __syncthreads();
    const float c = s_c, invc = 1.f / c;
    float* Y = sA[0]; float* Z = sA[1]; float* U = sA[2]; float* V = sA[3]; float* P = sA[4];
    Y[i * 33 + j] = cij * invc;
    Z[i * 33 + j] = (i == j) ? 1.f : 0.f;
    __syncthreads();
    for (int it = 0; it < 6; it++) {
        float a = 0.f;
        #pragma unroll
        for (int k = 0; k < 32; k++) a += Z[i * 33 + k] * Y[k * 33 + j];
        P[i * 33 + j] = ((i == j) ? 1.5f : 0.f) - 0.5f * a;
        __syncthreads();
        float a1 = 0.f, a2 = 0.f;
        #pragma unroll
        for (int k = 0; k < 32; k++) {
            a1 += Y[i * 33 + k] * P[k * 33 + j];
            a2 += P[i * 33 + k] * Z[k * 33 + j];
        }
        U[i * 33 + j] = a1;
        V[i * 33 + j] = a2;
        __syncthreads();
        float* t;
        t = Y; Y = U; U = t;
        t = Z; Z = V; V = t;
    }
    const float sc = sqrtf(c), isc = rsqrtf(c);
    g_Cp[cn * 1024 + i * 32 + j] = Y[i * 33 + j] * sc;
    g_Cm[cn * 1024 + i * 32 + j] = Z[i * 33 + j] * isc;
}

// ============================================================================
// Kernel 2: weighted per-distinct-sample logm via 2-node quadrature.
// One warp per (slot, cn). Packed f32x2; pivot row broadcast via SHFL
// (no syncwarp / shared memory in the pivot loop).
// ============================================================================
__global__ void __launch_bounds__(256, 3) main_kernel(const float* __restrict__ X) {
    __shared__ __align__(16) float sCm[32 * 36];        // stride 36 (16B-aligned rows)
    __shared__ __align__(16) float sBuf[WPB][32 * 36];  // per-warp matrix (row = lane)
    const int tid = threadIdx.x, warp = tid >> 5, lane = tid & 31;
    const int cn = blockIdx.y;
    const int slot = blockIdx.x * WPB + warp;

    for (int k = tid; k < 1024; k += 256)
        sCm[(k >> 5) * 36 + (k & 31)] = g_Cm[cn * 1024 + k];
    __syncthreads();

    float* bufrow = sBuf[warp] + lane * 36;
    pf4* br = (pf4*)bufrow;
    const float w = g_cnt[slot];

    if (w > 0.f) {
        const int xb = g_list[slot];
        const float* Xrow = X + (((size_t)xb * NCN + cn) << 10) + (lane << 5);

        // W = X * Cm (lane owns row `lane`); X streamed 4 floats at a time
        float2 wv[16];
        #pragma unroll
        for (int q = 0; q < 16; q++) wv[q] = make_float2(0.f, 0.f);
        #pragma unroll
        for (int kq = 0; kq < 8; kq++) {
            const float4 xv4 = ((const float4*)Xrow)[kq];
            #pragma unroll
            for (int kk = 0; kk < 4; kk++) {
                const float xv = f4c(xv4, kk);
                const float2 xv2 = make_float2(xv, xv);
                const pf4* cr = (const pf4*)(sCm + (4 * kq + kk) * 36);
                #pragma unroll
                for (int q = 0; q < 8; q++) {
                    pf4 v = cr[q];
                    wv[2 * q]     = ffma2(xv2, v.lo, wv[2 * q]);
                    wv[2 * q + 1] = ffma2(xv2, v.hi, wv[2 * q + 1]);
                }
            }
        }
        #pragma unroll
        for (int q = 0; q < 8; q++) {
            pf4 v; v.lo = wv[2 * q]; v.hi = wv[2 * q + 1];
            br[q] = v;
        }
        __syncwarp();

        // M = Cm * W (Cm symmetric: M[lane][j] = sum_k Cm[k][lane] * W[k][j])
        float2 m2[16];
        #pragma unroll
        for (int q = 0; q < 16; q++) m2[q] = make_float2(0.f, 0.f);
        #pragma unroll
        for (int k = 0; k < 32; k++) {
            const float cv = sCm[k * 36 + lane];
            const float2 cv2 = make_float2(cv, cv);
            const pf4* wr = (const pf4*)(sBuf[warp] + k * 36);
            #pragma unroll
            for (int q = 0; q < 8; q++) {
                pf4 v = wr[q];
                m2[2 * q]     = ffma2(cv2, v.lo, m2[2 * q]);
                m2[2 * q + 1] = ffma2(cv2, v.hi, m2[2 * q + 1]);
            }
        }
        __syncwarp();

        // logm(M) = SSUM*I - sum_nd wot_nd * (t_nd*M + (1-t_nd)*I)^{-1}
        #pragma unroll 1
        for (int nd = 0; nd < QN; nd++) {
            const float t = c_t[nd], wot = c_wot[nd];
            const float omt = 1.f - t;
            float2 B2[16];
            #pragma unroll
            for (int q = 0; q < 16; q++) {
                B2[q].x = t * m2[q].x + ((lane == 2 * q)     ? omt : 0.f);
                B2[q].y = t * m2[q].y + ((lane == 2 * q + 1) ? omt : 0.f);
            }

            // pivot-free Gauss-Jordan inverse, SHFL pivot-row broadcast
            #pragma unroll
            for (int k = 0; k < 32; k++) {
                // pivot element + own column-k element
                const float pivx = __shfl_sync(0xffffffffu, B2[k >> 1].x, k);
                const float pivy = __shfl_sync(0xffffffffu, B2[k >> 1].y, k);
                const float piv = (k & 1) ? pivy : pivx;
                const float ip = __fdividef(1.f, piv);
                const float bk = (k & 1) ? B2[k >> 1].y : B2[k >> 1].x;
                const float f = bk - ((lane == k) ? 1.f : 0.f);
                const float fp = f * ip;
                const float2 nfp2 = make_float2(-fp, -fp);
                #pragma unroll
                for (int q = 0; q < 16; q++) {
                    float2 pr;
                    pr.x = __shfl_sync(0xffffffffu, B2[q].x, k);
                    pr.y = __shfl_sync(0xffffffffu, B2[q].y, k);
                    B2[q] = ffma2(nfp2, pr, B2[q]);
                }
                const float nv = (lane == k) ? ip : -fp;
                if (k & 1) B2[k >> 1].y = nv; else B2[k >> 1].x = nv;
            }

            // accumulate -wot * Binv into own sBuf row
            const float2 nwot2 = make_float2(-wot, -wot);
            const float2 zero2 = make_float2(0.f, 0.f);
            if (nd == 0) {
                #pragma unroll
                for (int q = 0; q < 8; q++) {
                    pf4 v;
                    v.lo = ffma2(nwot2, B2[2 * q], zero2);
                    v.hi = ffma2(nwot2, B2[2 * q + 1], zero2);
                    br[q] = v;
                }
            } else {
                #pragma unroll
                for (int q = 0; q < 8; q++) {
                    pf4 v = br[q];
                    v.lo = ffma2(nwot2, B2[2 * q], v.lo);
                    v.hi = ffma2(nwot2, B2[2 * q + 1], v.hi);
                    br[q] = v;
                }
            }
        }

        // scale row by weight and add w*SSUM on the diagonal
        const float2 w2 = make_float2(w, w);
        const float2 zero2 = make_float2(0.f, 0.f);
        #pragma unroll
        for (int q = 0; q < 8; q++) {
            pf4 v = br[q];
            v.lo = ffma2(w2, v.lo, zero2);
            v.hi = ffma2(w2, v.hi, zero2);
            br[q] = v;
        }
        bufrow[lane] += w * SSUM;
    } else {
        pf4 z; z.lo = make_float2(0.f, 0.f); z.hi = z.lo;
        #pragma unroll
        for (int q = 0; q < 8; q++) br[q] = z;
    }
    __syncthreads();

    // deterministic block reduction over the 8 warps -> partial buffer
    float* outp = g_partial + ((size_t)blockIdx.x * NCN + cn) * 1024;
    for (int e = tid; e < 1024; e += 256) {
        const int r = e >> 5, cc = e & 31;
        float s = 0.f;
        #pragma unroll
        for (int wp = 0; wp < WPB; wp++) s += sBuf[wp][r * 36 + cc];
        outp[e] = s;
    }
}

// ============================================================================
// Kernel 3: chunk reduction, L_m = mean*ETA, Jacobi eigendecomp,
// E = Q diag(sign(l)*exp(|l|)) Q^T (matches the SVD-based "expm"),
// C_new = C^{1/2} E C^{1/2}.  grid(32), block(256).
// ============================================================================
__global__ void final_kernel(float* __restrict__ out) {
    __shared__ float sA[32 * 33];
    __shared__ float sQ[32 * 33];
    __shared__ float sCp[32 * 33];
    __shared__ float sE[32 * 33];
    __shared__ float sU[32 * 33];
    __shared__ float gl[32];
    __shared__ float rc[16], rs[16];
    __shared__ int   rp[16], rq[16];
    const int cn = blockIdx.x, tid = threadIdx.x;

    for (int e = tid; e < 1024; e += 256) {
        float s = 0.f;
        const float* pp = g_partial + cn * 1024 + e;
        for (int c = 0; c < NCHUNK; c++) s += pp[(size_t)c * NCN * 1024];
        const int i = e >> 5, j = e & 31;
        sA[i * 33 + j] = s * (0.01f / 1024.f);   // ETA / NB
        sQ[i * 33 + j] = (i == j) ? 1.f : 0.f;
        sCp[i * 33 + j] = g_Cp[cn * 1024 + e];
    }
    __syncthreads();

    for (int sweep = 0; sweep < 8; sweep++) {
        for (int r = 0; r < 31; r++) {
            if (tid < 16) {
                int p, q;
                if (tid == 0) { p = 31; q = r; }
                else { p = (r + tid) % 31; q = (r - tid + 31) % 31; }
                const float app = sA[p * 33 + p];
                const float aqq = sA[q * 33 + q];
                const float apq = sA[p * 33 + q];
                float cc = 1.f, ss = 0.f;
                if (apq != 0.f) {
                    const float theta = (aqq - app) / (2.f * apq);
                    const float tt = copysignf(1.f, theta) /
                                     (fabsf(theta) + sqrtf(theta * theta + 1.f));
                    cc = rsqrtf(tt * tt + 1.f);
                    ss = tt * cc;
                }
                rp[tid] = p; rq[tid] = q; rc[tid] = cc; rs[tid] = ss;
            }
            __syncthreads();
            for (int task = tid; task < 512; task += 256) {
                const int pr = task >> 5, row = task & 31;
                const int p = rp[pr], q = rq[pr];
                const float cc = rc[pr], ss = rs[pr];
                const float ap = sA[row * 33 + p], aq = sA[row * 33 + q];
                sA[row * 33 + p] = cc * ap - ss * aq;
                sA[row * 33 + q] = ss * ap + cc * aq;
                const float qp = sQ[row * 33 + p], qq = sQ[row * 33 + q];
                sQ[row * 33 + p] = cc * qp - ss * qq;
                sQ[row * 33 + q] = ss * qp + cc * qq;
            }
            __syncthreads();
            for (int task = tid; task < 512; task += 256) {
                const int pr = task >> 5, col = task & 31;
                const int p = rp[pr], q = rq[pr];
                const float cc = rc[pr], ss = rs[pr];
                const float ap = sA[p * 33 + col], aq = sA[q * 33 + col];
                sA[p * 33 + col] = cc * ap - ss * aq;
                sA[q * 33 + col] = ss * ap + cc * aq;
            }
            __syncthreads();
        }
    }

    if (tid < 32) {
        const float lam = sA[tid * 33 + tid];
        gl[tid] = copysignf(expf(fabsf(lam)), lam);
    }
    __syncthreads();

    for (int e = tid; e < 1024; e += 256) {
        const int i = e >> 5, j = e & 31;
        float s = 0.f;
        #pragma unroll
        for (int k = 0; k < 32; k++)
            s = fmaf(sQ[i * 33 + k] * gl[k], sQ[j * 33 + k], s);
        sE[i * 33 + j] = s;
    }
    __syncthreads();

    for (int e = tid; e < 1024; e += 256) {
        const int i = e >> 5, j = e & 31;
        float s = 0.f;
        #pragma unroll
        for (int k = 0; k < 32; k++)
            s = fmaf(sE[i * 33 + k], sCp[k * 33 + j], s);
        sU[i * 33 + j] = s;
    }
    __syncthreads();

    for (int e = tid; e < 1024; e += 256) {
        const int i = e >> 5, j = e & 31;
        float s = 0.f;
        #pragma unroll
        for (int k = 0; k < 32; k++)
            s = fmaf(sCp[i * 33 + k], sU[k * 33 + j], s);
        out[cn * 1024 + e] = s;
    }
}

// ============================================================================
extern "C" void kernel_launch(void* const* d_in, const int* in_sizes, int n_in,
                              void* d_out, int out_size) {
    const float* X = nullptr;
    const float* C = nullptr;
    const int* idx = nullptr;
    int xElems = 0;
    for (int i = 0; i < n_in; i++) {
        if (in_sizes[i] == NB) idx = (const int*)d_in[i];
        else if (in_sizes[i] == NCN * 1024) C = (const float*)d_in[i];
        else { X = (const float*)d_in[i]; xElems = in_sizes[i]; }
    }
    const int batch = xElems / (NCN * 1024);

    if (batch == NBINS) {
        dedup_kernel<<<1, 1024>>>(idx);
    } else {
        nodedup_kernel<<<1, NB>>>(idx);
    }
    prep_kernel<<<NCN, 1024>>>(C);
    dim3 grid(NCHUNK, NCN);
    main_kernel<<<grid, 256>>>(X);
    final_kernel<<<NCN, 256>>>((float*)d_out);
}

// round 5
// speedup vs baseline: 2.5640x; 1.1310x over previous
#include <cuda_runtime.h>
#include <cstdint>
#include <cstddef>

#define NCN    32      // 2*16 centroid matrices
#define NB     1024    // number of sampled indices
#define NBINS  2048    // batch size B (histogram bins)
#define NCHUNK 128     // b-chunks in main kernel grid
#define WPB    8       // warps per block (main kernel)
#define QN     2       // Gauss-Legendre nodes for logm
#define SSUM   3.0f    // sum of w_i/t_i for GL-2 on [0,1] (exactly 3)
#define SWEEPS 8       // Jacobi sweeps

// ---- scratch (static device globals; no allocation APIs) ----
__device__ float g_Cp[NCN * 1024];                    // C^{+1/2}
__device__ float g_partial[NCHUNK * NCN * 1024];      // per-chunk partial sums of w*wot*Binv
__device__ int   g_list[NB];                          // distinct xb values (ascending)
__device__ float g_cnt[NB];                           // multiplicity weights (0 = idle slot)

// Gauss-Legendre 2-node on [0,1]
__constant__ float c_t[QN]   = {0.21132486540518713f, 0.78867513459481287f};
__constant__ float c_wot[QN] = {2.3660254037844384f, 0.6339745962155614f};

// ---- packed f32x2 helpers ----
union f2u { float2 f; unsigned long long u; };
__device__ __forceinline__ float2 ffma2(float2 a, float2 b, float2 c) {
    f2u A, B, C, R; A.f = a; B.f = b; C.f = c;
    asm("fma.rn.f32x2 %0, %1, %2, %3;" : "=l"(R.u) : "l"(A.u), "l"(B.u), "l"(C.u));
    return R.f;
}
struct __align__(16) pf4 { float2 lo, hi; };

// ============================================================================
// Dedup in one launch: smem histogram + ordered compaction (deterministic).
// ============================================================================
__global__ void dedup_kernel(const int* __restrict__ idx) {
    __shared__ int h[NBINS];
    __shared__ int s1[1024], s2[1024];
    const int t = threadIdx.x;
    h[t] = 0; h[t + 1024] = 0;
    g_list[t] = 0; g_cnt[t] = 0.f;
    __syncthreads();
    atomicAdd(&h[idx[t]], 1);
    __syncthreads();
    const int h0 = h[2 * t], h1 = h[2 * t + 1];
    const int p0 = h0 > 0, p1 = h1 > 0;
    s1[t] = p0 + p1;
    __syncthreads();
    int* src = s1; int* dst = s2;
    for (int off = 1; off < 1024; off <<= 1) {
        int v = src[t];
        if (t >= off) v += src[t - off];
        dst[t] = v;
        __syncthreads();
        int* tmp = src; src = dst; dst = tmp;
    }
    const int excl = src[t] - (p0 + p1);
    if (p0) { g_list[excl] = 2 * t;          g_cnt[excl] = (float)h0; }
    if (p1) { g_list[excl + p0] = 2 * t + 1; g_cnt[excl + p0] = (float)h1; }
}
__global__ void nodedup_kernel(const int* __restrict__ idx) {
    g_list[threadIdx.x] = idx[threadIdx.x];
    g_cnt[threadIdx.x] = 1.f;
}

// ============================================================================
// Kernel 1: C^{+1/2} via coupled Newton-Schulz sqrt iteration.
// ============================================================================
__global__ void prep_kernel(const float* __restrict__ C) {
    __shared__ float sA[5][32 * 33];
    __shared__ float s_c;
    const int cn = blockIdx.x, tid = threadIdx.x;
    const int i = tid >> 5, j = tid & 31;
    const float cij = C[cn * 1024 + i * 32 + j];
    if (tid == 0) {
        float s = 0.f;
        #pragma unroll
        for (int k = 0; k < 32; k++) s += C[cn * 1024 + k * 33];
        s_c = s * (1.f / 32.f);
    }
    __syncthreads();
    const float c = s_c, invc = 1.f / c;
    float* Y = sA[0]; float* Z = sA[1]; float* U = sA[2]; float* V = sA[3]; float* P = sA[4];
    Y[i * 33 + j] = cij * invc;
    Z[i * 33 + j] = (i == j) ? 1.f : 0.f;
    __syncthreads();
    for (int it = 0; it < 6; it++) {
        float a = 0.f;
        #pragma unroll
        for (int k = 0; k < 32; k++) a += Z[i * 33 + k] * Y[k * 33 + j];
        P[i * 33 + j] = ((i == j) ? 1.5f : 0.f) - 0.5f * a;
        __syncthreads();
        float a1 = 0.f, a2 = 0.f;
        #pragma unroll
        for (int k = 0; k < 32; k++) {
            a1 += Y[i * 33 + k] * P[k * 33 + j];
            a2 += P[i * 33 + k] * Z[k * 33 + j];
        }
        U[i * 33 + j] = a1;
        V[i * 33 + j] = a2;
        __syncthreads();
        float* t;
        t = Y; Y = U; U = t;
        t = Z; Z = V; V = t;
    }
    g_Cp[cn * 1024 + i * 32 + j] = Y[i * 33 + j] * sqrtf(c);
}

// ============================================================================
// Kernel 2: accumulate Binv = (t*X_b + (1-t)*C)^{-1} weighted by w_b*wot_nd.
// One warp per (slot, cn). No per-sample matmuls (similarity identity moves
// the C-conjugation into the final kernel). GJ inverse with LDS.128
// double-buffered pivot-row broadcast (1 syncwarp per pivot).
// ============================================================================
__global__ void __launch_bounds__(256, 3) main_kernel(const float* __restrict__ X,
                                                      const float* __restrict__ Cin) {
    __shared__ __align__(16) float sC[32 * 36];         // C rows (stride 36)
    __shared__ __align__(16) float sBuf[WPB][32 * 36];  // per-warp accumulator
    __shared__ __align__(16) float sBc[WPB][2][32];     // double-buffered pivot row
    const int tid = threadIdx.x, warp = tid >> 5, lane = tid & 31;
    const int cn = blockIdx.y;
    const int slot = blockIdx.x * WPB + warp;

    for (int k = tid; k < 1024; k += 256)
        sC[(k >> 5) * 36 + (k & 31)] = Cin[cn * 1024 + k];
    __syncthreads();

    float* bufrow = sBuf[warp] + lane * 36;
    pf4* br = (pf4*)bufrow;
    const float w = g_cnt[slot];

    if (w > 0.f) {
        const float* Xrow = X + (((size_t)g_list[slot] * NCN + cn) << 10) + (lane << 5);
        const pf4* crow = (const pf4*)(sC + lane * 36);

        #pragma unroll 1
        for (int nd = 0; nd < QN; nd++) {
            const float t = c_t[nd];
            const float2 t2 = make_float2(t, t);
            const float2 omt2 = make_float2(1.f - t, 1.f - t);

            // B = t*X + (1-t)*C   (row `lane` in registers)
            float2 B2[16];
            #pragma unroll
            for (int q = 0; q < 8; q++) {
                const float4 xv = ((const float4*)Xrow)[q];
                const pf4 cv = crow[q];
                float2 xlo = make_float2(xv.x, xv.y);
                float2 xhi = make_float2(xv.z, xv.w);
                B2[2 * q]     = ffma2(t2, xlo, make_float2(omt2.x * cv.lo.x, omt2.x * cv.lo.y));
                B2[2 * q + 1] = ffma2(t2, xhi, make_float2(omt2.x * cv.hi.x, omt2.x * cv.hi.y));
            }

            // pivot-free Gauss-Jordan inverse (B SPD, well conditioned)
            #pragma unroll
            for (int k = 0; k < 32; k++) {
                float* bc = sBc[warp][k & 1];
                if (lane == k) {
                    pf4* bp = (pf4*)bc;
                    #pragma unroll
                    for (int q = 0; q < 8; q++) {
                        pf4 v; v.lo = B2[2 * q]; v.hi = B2[2 * q + 1];
                        bp[q] = v;
                    }
                }
                __syncwarp();
                pf4 bv[8];
                const pf4* bp = (const pf4*)bc;
                #pragma unroll
                for (int q = 0; q < 8; q++) bv[q] = bp[q];
                const float piv = ((k >> 1) & 1)
                    ? ((k & 1) ? bv[k >> 2].hi.y : bv[k >> 2].hi.x)
                    : ((k & 1) ? bv[k >> 2].lo.y : bv[k >> 2].lo.x);
                const float ip = __fdividef(1.f, piv);
                const float bk = (k & 1) ? B2[k >> 1].y : B2[k >> 1].x;
                const float f = bk - ((lane == k) ? 1.f : 0.f);
                const float fp = f * ip;
                const float2 nfp2 = make_float2(-fp, -fp);
                #pragma unroll
                for (int q = 0; q < 8; q++) {
                    B2[2 * q]     = ffma2(nfp2, bv[q].lo, B2[2 * q]);
                    B2[2 * q + 1] = ffma2(nfp2, bv[q].hi, B2[2 * q + 1]);
                }
                const float nv = (lane == k) ? ip : -fp;
                if (k & 1) B2[k >> 1].y = nv; else B2[k >> 1].x = nv;
            }

            // accumulate (w*wot)*Binv into own sBuf row
            const float s = w * c_wot[nd];
            const float2 s2 = make_float2(s, s);
            if (nd == 0) {
                #pragma unroll
                for (int q = 0; q < 8; q++) {
                    pf4 v;
                    v.lo = make_float2(s2.x * B2[2 * q].x, s2.x * B2[2 * q].y);
                    v.hi = make_float2(s2.x * B2[2 * q + 1].x, s2.x * B2[2 * q + 1].y);
                    br[q] = v;
                }
            } else {
                #pragma unroll
                for (int q = 0; q < 8; q++) {
                    pf4 v = br[q];
                    v.lo = ffma2(s2, B2[2 * q], v.lo);
                    v.hi = ffma2(s2, B2[2 * q + 1], v.hi);
                    br[q] = v;
                }
            }
        }
    } else {
        pf4 z; z.lo = make_float2(0.f, 0.f); z.hi = z.lo;
        #pragma unroll
        for (int q = 0; q < 8; q++) br[q] = z;
    }
    __syncthreads();

    // deterministic block reduction over the 8 warps -> partial buffer
    float* outp = g_partial + ((size_t)blockIdx.x * NCN + cn) * 1024;
    for (int e = tid; e < 1024; e += 256) {
        const int r = e >> 5, cc = e & 31;
        float s = 0.f;
        #pragma unroll
        for (int wp = 0; wp < WPB; wp++) s += sBuf[wp][r * 36 + cc];
        outp[e] = s;
    }
}

// ============================================================================
// Kernel 3 (block = 1024, thread per element):
//   Abar = chunk-reduce / NB
//   L_m  = eta * (SSUM*I - Cp * Abar * Cp)        [symmetric]
//   Jacobi eigendecomp (fused J^T A J per round, 2 barriers/round)
//   E    = Q diag(sign(l)*exp(|l|)) Q^T           [matches SVD-based "expm"]
//   out  = Cp * E * Cp
// ============================================================================
__global__ void final_kernel(float* __restrict__ out) {
    __shared__ float sA[32 * 33], sB[32 * 33];
    __shared__ float sQ[32 * 33], sQ2[32 * 33];
    __shared__ float sCp[32 * 33], sT[32 * 33];
    __shared__ float al[32], be[32], gl[32];
    __shared__ int   part[32];
    const int cn = blockIdx.x, tid = threadIdx.x;
    const int i = tid >> 5, j = tid & 31;

    // chunk reduction -> Abar
    {
        float s = 0.f;
        const float* pp = g_partial + cn * 1024 + tid;
        for (int c = 0; c < NCHUNK; c++) s += pp[(size_t)c * NCN * 1024];
        sT[i * 33 + j] = s * (1.f / 1024.f);
        sCp[i * 33 + j] = g_Cp[cn * 1024 + tid];
    }
    __syncthreads();

    // sB = Abar * Cp
    {
        float s = 0.f;
        #pragma unroll
        for (int k = 0; k < 32; k++) s = fmaf(sT[i * 33 + k], sCp[k * 33 + j], s);
        sB[i * 33 + j] = s;
    }
    __syncthreads();

    // L_m = eta*(SSUM*I - Cp*(Abar*Cp)) -> sA ; Q = I
    {
        float s = 0.f;
        #pragma unroll
        for (int k = 0; k < 32; k++) s = fmaf(sCp[i * 33 + k], sB[k * 33 + j], s);
        sA[i * 33 + j] = 0.01f * (((i == j) ? SSUM : 0.f) - s);
        sQ[i * 33 + j] = (i == j) ? 1.f : 0.f;
    }
    __syncthreads();

    // parallel two-sided Jacobi, fused J^T A J (ping-pong), 2 barriers/round
    for (int sweep = 0; sweep < SWEEPS; sweep++) {
        for (int r = 0; r < 31; r++) {
            const int rr = sweep * 31 + r;
            float* cur  = (rr & 1) ? sB : sA;
            float* nxt  = (rr & 1) ? sA : sB;
            float* curQ = (rr & 1) ? sQ2 : sQ;
            float* nxtQ = (rr & 1) ? sQ : sQ2;
            if (tid < 16) {
                int p, q;
                if (tid == 0) { p = 31; q = r; }
                else { p = (r + tid) % 31; q = (r - tid + 31) % 31; }
                const float app = cur[p * 33 + p];
                const float aqq = cur[q * 33 + q];
                const float apq = cur[p * 33 + q];
                float cc = 1.f, ss = 0.f;
                if (apq != 0.f) {
                    const float theta = (aqq - app) / (2.f * apq);
                    const float tt = copysignf(1.f, theta) /
                                     (fabsf(theta) + sqrtf(theta * theta + 1.f));
                    cc = rsqrtf(tt * tt + 1.f);
                    ss = tt * cc;
                }
                part[p] = q; part[q] = p;
                al[p] = cc; al[q] = cc;
                be[p] = -ss; be[q] = ss;
            }
            __syncthreads();
            {
                const int pi = part[i], pj = part[j];
                const float ai = al[i], bi = be[i];
                const float aj = al[j], bj = be[j];
                const float a00 = cur[i * 33 + j],  a01 = cur[i * 33 + pj];
                const float a10 = cur[pi * 33 + j], a11 = cur[pi * 33 + pj];
                nxt[i * 33 + j] = ai * (aj * a00 + bj * a01) + bi * (aj * a10 + bj * a11);
                const float q0 = curQ[i * 33 + j], q1 = curQ[i * 33 + pj];
                nxtQ[i * 33 + j] = aj * q0 + bj * q1;
            }
            __syncthreads();
        }
    }
    // SWEEPS*31 = 248 rounds (even) -> result in sA / sQ

    if (tid < 32) {
        const float lam = sA[tid * 33 + tid];
        gl[tid] = copysignf(expf(fabsf(lam)), lam);
    }
    __syncthreads();

    // E = Q diag(gl) Q^T  -> sB
    {
        float s = 0.f;
        #pragma unroll
        for (int k = 0; k < 32; k++)
            s = fmaf(sQ[i * 33 + k] * gl[k], sQ[j * 33 + k], s);
        sB[i * 33 + j] = s;
    }
    __syncthreads();

    // U = E * Cp -> sT
    {
        float s = 0.f;
        #pragma unroll
        for (int k = 0; k < 32; k++) s = fmaf(sB[i * 33 + k], sCp[k * 33 + j], s);
        sT[i * 33 + j] = s;
    }
    __syncthreads();

    // out = Cp * U
    {
        float s = 0.f;
        #pragma unroll
        for (int k = 0; k < 32; k++) s = fmaf(sCp[i * 33 + k], sT[k * 33 + j], s);
        out[cn * 1024 + tid] = s;
    }
}

// ============================================================================
extern "C" void kernel_launch(void* const* d_in, const int* in_sizes, int n_in,
                              void* d_out, int out_size) {
    const float* X = nullptr;
    const float* C = nullptr;
    const int* idx = nullptr;
    int xElems = 0;
    for (int i = 0; i < n_in; i++) {
        if (in_sizes[i] == NB) idx = (const int*)d_in[i];
        else if (in_sizes[i] == NCN * 1024) C = (const float*)d_in[i];
        else { X = (const float*)d_in[i]; xElems = in_sizes[i]; }
    }
    const int batch = xElems / (NCN * 1024);

    if (batch == NBINS) {
        dedup_kernel<<<1, 1024>>>(idx);
    } else {
        nodedup_kernel<<<1, NB>>>(idx);
    }
    prep_kernel<<<NCN, 1024>>>(C);
    dim3 grid(NCHUNK, NCN);
    main_kernel<<<grid, 256>>>(X, C);
    final_kernel<<<NCN, 1024>>>((float*)d_out);
}

// round 6
// speedup vs baseline: 3.4876x; 1.3602x over previous
#include <cuda_runtime.h>
#include <cstdint>
#include <cstddef>

#define NCN    32      // 2*16 centroid matrices
#define NB     1024    // number of sampled indices
#define NBINS  2048    // batch size B (histogram bins)
#define NCHUNK 128     // b-chunks in main kernel grid
#define WPB    8       // warps per block (main kernel)
#define SSUM   3.0f    // sum of w_i/t_i for GL-2 on [0,1] (exactly 3)
#define NSIT   22      // Newton-Schulz sign iterations

// ---- scratch (static device globals; no allocation APIs) ----
__device__ float g_Cp[NCN * 1024];                    // C^{+1/2}
__device__ float g_partial[NCHUNK * NCN * 1024];      // per-chunk partial sums of w*wot*Binv
__device__ int   g_list[NB];                          // distinct xb values (ascending)
__device__ float g_cnt[NB];                           // multiplicity weights (0 = idle slot)

// Gauss-Legendre 2-node on [0,1]
#define T0   0.21132486540518713f
#define T1   0.78867513459481287f
#define WOT0 2.3660254037844384f
#define WOT1 0.6339745962155614f

// ---- packed f32x2 helpers ----
union f2u { float2 f; unsigned long long u; };
__device__ __forceinline__ float2 ffma2(float2 a, float2 b, float2 c) {
    f2u A, B, C, R; A.f = a; B.f = b; C.f = c;
    asm("fma.rn.f32x2 %0, %1, %2, %3;" : "=l"(R.u) : "l"(A.u), "l"(B.u), "l"(C.u));
    return R.f;
}
struct __align__(16) pf4 { float2 lo, hi; };

// ============================================================================
// Dedup in one launch: smem histogram + ordered compaction (deterministic).
// ============================================================================
__global__ void dedup_kernel(const int* __restrict__ idx) {
    __shared__ int h[NBINS];
    __shared__ int s1[1024], s2[1024];
    const int t = threadIdx.x;
    h[t] = 0; h[t + 1024] = 0;
    g_list[t] = 0; g_cnt[t] = 0.f;
    __syncthreads();
    atomicAdd(&h[idx[t]], 1);
    __syncthreads();
    const int h0 = h[2 * t], h1 = h[2 * t + 1];
    const int p0 = h0 > 0, p1 = h1 > 0;
    s1[t] = p0 + p1;
    __syncthreads();
    int* src = s1; int* dst = s2;
    for (int off = 1; off < 1024; off <<= 1) {
        int v = src[t];
        if (t >= off) v += src[t - off];
        dst[t] = v;
        __syncthreads();
        int* tmp = src; src = dst; dst = tmp;
    }
    const int excl = src[t] - (p0 + p1);
    if (p0) { g_list[excl] = 2 * t;          g_cnt[excl] = (float)h0; }
    if (p1) { g_list[excl + p0] = 2 * t + 1; g_cnt[excl + p0] = (float)h1; }
}
__global__ void nodedup_kernel(const int* __restrict__ idx) {
    g_list[threadIdx.x] = idx[threadIdx.x];
    g_cnt[threadIdx.x] = 1.f;
}

// ============================================================================
// Kernel 1: C^{+1/2} via coupled Newton-Schulz sqrt iteration.
// ============================================================================
__global__ void prep_kernel(const float* __restrict__ C) {
    __shared__ float sA[5][32 * 33];
    __shared__ float s_c;
    const int cn = blockIdx.x, tid = threadIdx.x;
    const int i = tid >> 5, j = tid & 31;
    const float cij = C[cn * 1024 + i * 32 + j];
    if (tid == 0) {
        float s = 0.f;
        #pragma unroll
        for (int k = 0; k < 32; k++) s += C[cn * 1024 + k * 33];
        s_c = s * (1.f / 32.f);
    }
    __syncthreads();
    const float c = s_c, invc = 1.f / c;
    float* Y = sA[0]; float* Z = sA[1]; float* U = sA[2]; float* V = sA[3]; float* P = sA[4];
    Y[i * 33 + j] = cij * invc;
    Z[i * 33 + j] = (i == j) ? 1.f : 0.f;
    __syncthreads();
    for (int it = 0; it < 6; it++) {
        float a = 0.f;
        #pragma unroll
        for (int k = 0; k < 32; k++) a += Z[i * 33 + k] * Y[k * 33 + j];
        P[i * 33 + j] = ((i == j) ? 1.5f : 0.f) - 0.5f * a;
        __syncthreads();
        float a1 = 0.f, a2 = 0.f;
        #pragma unroll
        for (int k = 0; k < 32; k++) {
            a1 += Y[i * 33 + k] * P[k * 33 + j];
            a2 += P[i * 33 + k] * Z[k * 33 + j];
        }
        U[i * 33 + j] = a1;
        V[i * 33 + j] = a2;
        __syncthreads();
        float* t;
        t = Y; Y = U; U = t;
        t = Z; Z = V; V = t;
    }
    g_Cp[cn * 1024 + i * 32 + j] = Y[i * 33 + j] * sqrtf(c);
}

// ============================================================================
// Kernel 2: accumulate w*(wot0*inv(B0) + wot1*inv(B1)), B_nd = t_nd*X+(1-t_nd)*C.
// Both quadrature nodes' Gauss-Jordan eliminations interleaved in ONE pivot
// loop (halves pivot-chain latency exposure, doubles ILP).
// ============================================================================
__global__ void __launch_bounds__(256, 2) main_kernel(const float* __restrict__ X,
                                                      const float* __restrict__ Cin) {
    __shared__ __align__(16) float sC[32 * 36];             // C rows (stride 36)
    __shared__ __align__(16) float sBuf[WPB][32 * 36];      // per-warp accumulator
    __shared__ __align__(16) float sBc[WPB][2][2][32];      // [warp][parity][node][row]
    const int tid = threadIdx.x, warp = tid >> 5, lane = tid & 31;
    const int cn = blockIdx.y;
    const int slot = blockIdx.x * WPB + warp;

    for (int k = tid; k < 1024; k += 256)
        sC[(k >> 5) * 36 + (k & 31)] = Cin[cn * 1024 + k];
    __syncthreads();

    float* bufrow = sBuf[warp] + lane * 36;
    pf4* br = (pf4*)bufrow;
    const float w = g_cnt[slot];

    if (w > 0.f) {
        const float* Xrow = X + (((size_t)g_list[slot] * NCN + cn) << 10) + (lane << 5);
        const pf4* crow = (const pf4*)(sC + lane * 36);

        // Build both B matrices (row `lane` in registers)
        float2 Ba[16], Bb[16];
        {
            const float2 ta = make_float2(T0, T0), tb = make_float2(T1, T1);
            const float oa = 1.f - T0, ob = 1.f - T1;
            #pragma unroll
            for (int q = 0; q < 8; q++) {
                const float4 xv = ((const float4*)Xrow)[q];
                const pf4 cv = crow[q];
                const float2 xlo = make_float2(xv.x, xv.y);
                const float2 xhi = make_float2(xv.z, xv.w);
                Ba[2 * q]     = ffma2(ta, xlo, make_float2(oa * cv.lo.x, oa * cv.lo.y));
                Ba[2 * q + 1] = ffma2(ta, xhi, make_float2(oa * cv.hi.x, oa * cv.hi.y));
                Bb[2 * q]     = ffma2(tb, xlo, make_float2(ob * cv.lo.x, ob * cv.lo.y));
                Bb[2 * q + 1] = ffma2(tb, xhi, make_float2(ob * cv.hi.x, ob * cv.hi.y));
            }
        }

        // dual pivot-free Gauss-Jordan inverse (both SPD, well conditioned)
        #pragma unroll
        for (int k = 0; k < 32; k++) {
            float* bcA = sBc[warp][k & 1][0];
            float* bcB = sBc[warp][k & 1][1];
            if (lane == k) {
                pf4* pA = (pf4*)bcA;
                pf4* pB = (pf4*)bcB;
                #pragma unroll
                for (int q = 0; q < 8; q++) {
                    pf4 va; va.lo = Ba[2 * q]; va.hi = Ba[2 * q + 1];
                    pf4 vb; vb.lo = Bb[2 * q]; vb.hi = Bb[2 * q + 1];
                    pA[q] = va; pB[q] = vb;
                }
            }
            __syncwarp();
            const float pivA = bcA[k], pivB = bcB[k];
            const float ipA = __fdividef(1.f, pivA);
            const float ipB = __fdividef(1.f, pivB);
            const float one = (lane == k) ? 1.f : 0.f;
            const float bkA = (k & 1) ? Ba[k >> 1].y : Ba[k >> 1].x;
            const float bkB = (k & 1) ? Bb[k >> 1].y : Bb[k >> 1].x;
            const float fpA = (bkA - one) * ipA;
            const float fpB = (bkB - one) * ipB;
            const float2 nA = make_float2(-fpA, -fpA);
            const float2 nB = make_float2(-fpB, -fpB);
            const pf4* pA = (const pf4*)bcA;
            const pf4* pB = (const pf4*)bcB;
            #pragma unroll
            for (int q = 0; q < 8; q++) {
                const pf4 va = pA[q];
                const pf4 vb = pB[q];
                Ba[2 * q]     = ffma2(nA, va.lo, Ba[2 * q]);
                Ba[2 * q + 1] = ffma2(nA, va.hi, Ba[2 * q + 1]);
                Bb[2 * q]     = ffma2(nB, vb.lo, Bb[2 * q]);
                Bb[2 * q + 1] = ffma2(nB, vb.hi, Bb[2 * q + 1]);
            }
            const float nvA = (lane == k) ? ipA : -fpA;
            const float nvB = (lane == k) ? ipB : -fpB;
            if (k & 1) { Ba[k >> 1].y = nvA; Bb[k >> 1].y = nvB; }
            else       { Ba[k >> 1].x = nvA; Bb[k >> 1].x = nvB; }
        }

        // acc = w*(WOT0*invA + WOT1*invB) into own sBuf row
        const float2 sa = make_float2(w * WOT0, w * WOT0);
        const float2 sb = make_float2(w * WOT1, w * WOT1);
        const float2 z2 = make_float2(0.f, 0.f);
        #pragma unroll
        for (int q = 0; q < 8; q++) {
            pf4 v;
            v.lo = ffma2(sa, Ba[2 * q],     ffma2(sb, Bb[2 * q],     z2));
            v.hi = ffma2(sa, Ba[2 * q + 1], ffma2(sb, Bb[2 * q + 1], z2));
            br[q] = v;
        }
    } else {
        pf4 z; z.lo = make_float2(0.f, 0.f); z.hi = z.lo;
        #pragma unroll
        for (int q = 0; q < 8; q++) br[q] = z;
    }
    __syncthreads();

    // deterministic block reduction over the 8 warps -> partial buffer
    float* outp = g_partial + ((size_t)blockIdx.x * NCN + cn) * 1024;
    for (int e = tid; e < 1024; e += 256) {
        const int r = e >> 5, cc = e & 31;
        float s = 0.f;
        #pragma unroll
        for (int wp = 0; wp < WPB; wp++) s += sBuf[wp][r * 36 + cc];
        outp[e] = s;
    }
}

// ============================================================================
// Kernel 3 (block = 1024, thread per element):
//   Abar = chunk-reduce / NB
//   L    = eta*(SSUM*I - Cp*Abar*Cp)                [symmetric, ||L|| ~ 5e-3]
//   S    = sgn(L) via Frobenius-scaled Newton-Schulz (S <- 1.5S - 0.5 S^3)
//   E    = S*cosh(L) + sinh(L)   ==  Q sign(Lam) exp(|Lam|) Q^T
//   out  = Cp * E * Cp
// ============================================================================
__global__ void final_kernel(float* __restrict__ out) {
    __shared__ float sCp[32 * 33], sL[32 * 33];
    __shared__ float sSa[32 * 33], sSb[32 * 33];
    __shared__ float sT[32 * 33], sU[32 * 33];
    __shared__ float sRed[32];
    __shared__ float s_ialpha;
    const int cn = blockIdx.x, tid = threadIdx.x;
    const int i = tid >> 5, j = tid & 31;
    const int ro = i * 33;   // row offset

    // chunk reduction -> Abar (sT) ; load Cp
    {
        float s = 0.f;
        const float* pp = g_partial + cn * 1024 + tid;
        for (int c = 0; c < NCHUNK; c++) s += pp[(size_t)c * NCN * 1024];
        sT[ro + j] = s * (1.f / 1024.f);
        sCp[ro + j] = g_Cp[cn * 1024 + tid];
    }
    __syncthreads();

    // sU = Abar * Cp
    {
        float s = 0.f;
        #pragma unroll
        for (int k = 0; k < 32; k++) s = fmaf(sT[ro + k], sCp[k * 33 + j], s);
        sU[ro + j] = s;
    }
    __syncthreads();

    // L = eta*(SSUM*I - Cp*U); also Frobenius-norm reduction
    float lv;
    {
        float s = 0.f;
        #pragma unroll
        for (int k = 0; k < 32; k++) s = fmaf(sCp[ro + k], sU[k * 33 + j], s);
        lv = 0.01f * (((i == j) ? SSUM : 0.f) - s);
        sL[ro + j] = lv;
    }
    // warp (row) reduction of lv^2, then cross-warp
    {
        float v = lv * lv;
        #pragma unroll
        for (int o = 16; o > 0; o >>= 1) v += __shfl_xor_sync(0xffffffffu, v, o);
        if (j == 0) sRed[i] = v;
    }
    __syncthreads();
    if (tid < 32) {
        float v = sRed[tid];
        #pragma unroll
        for (int o = 16; o > 0; o >>= 1) v += __shfl_xor_sync(0xffffffffu, v, o);
        if (tid == 0) s_ialpha = rsqrtf(v + 1e-30f);
    }
    __syncthreads();

    // S0 = L / ||L||_F
    sSa[ro + j] = lv * s_ialpha;
    __syncthreads();

    // Newton-Schulz sign iteration: S <- 1.5 S - 0.5 S^3
    float* S  = sSa;
    float* Sn = sSb;
    for (int it = 0; it < NSIT; it++) {
        {   // sT = S * S
            float s = 0.f;
            #pragma unroll
            for (int k = 0; k < 32; k++) s = fmaf(S[ro + k], S[k * 33 + j], s);
            sT[ro + j] = s;
        }
        __syncthreads();
        {   // Sn = 1.5 S - 0.5 S*T
            float s = 0.f;
            #pragma unroll
            for (int k = 0; k < 32; k++) s = fmaf(S[ro + k], sT[k * 33 + j], s);
            Sn[ro + j] = 1.5f * S[ro + j] - 0.5f * s;
        }
        __syncthreads();
        float* tmp = S; S = Sn; Sn = tmp;
    }
    // S = sgn(L); Sn is free scratch.

    // P2 = L*L -> sT
    {
        float s = 0.f;
        #pragma unroll
        for (int k = 0; k < 32; k++) s = fmaf(sL[ro + k], sL[k * 33 + j], s);
        sT[ro + j] = s;
    }
    __syncthreads();
    // sinh(L) ~= L + L*P2/6 -> sU ;  (P4 term via in-register P2 row reuse)
    {
        float s = 0.f;
        #pragma unroll
        for (int k = 0; k < 32; k++) s = fmaf(sL[ro + k], sT[k * 33 + j], s);
        sU[ro + j] = fmaf(s, (1.f / 6.f), sL[ro + j]);
    }
    __syncthreads();
    // cosh(L) ~= I + P2/2 + P2*P2/24 -> Sn
    {
        float s = 0.f;
        #pragma unroll
        for (int k = 0; k < 32; k++) s = fmaf(sT[ro + k], sT[k * 33 + j], s);
        Sn[ro + j] = ((i == j) ? 1.f : 0.f) + 0.5f * sT[ro + j] + s * (1.f / 24.f);
    }
    __syncthreads();
    // E = S*cosh + sinh -> sT
    {
        float s = 0.f;
        #pragma unroll
        for (int k = 0; k < 32; k++) s = fmaf(S[ro + k], Sn[k * 33 + j], s);
        sT[ro + j] = s + sU[ro + j];
    }
    __syncthreads();
    // V = E * Cp -> sU
    {
        float s = 0.f;
        #pragma unroll
        for (int k = 0; k < 32; k++) s = fmaf(sT[ro + k], sCp[k * 33 + j], s);
        sU[ro + j] = s;
    }
    __syncthreads();
    // out = Cp * V
    {
        float s = 0.f;
        #pragma unroll
        for (int k = 0; k < 32; k++) s = fmaf(sCp[ro + k], sU[k * 33 + j], s);
        out[cn * 1024 + tid] = s;
    }
}

// ============================================================================
extern "C" void kernel_launch(void* const* d_in, const int* in_sizes, int n_in,
                              void* d_out, int out_size) {
    const float* X = nullptr;
    const float* C = nullptr;
    const int* idx = nullptr;
    int xElems = 0;
    for (int i = 0; i < n_in; i++) {
        if (in_sizes[i] == NB) idx = (const int*)d_in[i];
        else if (in_sizes[i] == NCN * 1024) C = (const float*)d_in[i];
        else { X = (const float*)d_in[i]; xElems = in_sizes[i]; }
    }
    const int batch = xElems / (NCN * 1024);

    if (batch == NBINS) {
        dedup_kernel<<<1, 1024>>>(idx);
    } else {
        nodedup_kernel<<<1, NB>>>(idx);
    }
    prep_kernel<<<NCN, 1024>>>(C);
    dim3 grid(NCHUNK, NCN);
    main_kernel<<<grid, 256>>>(X, C);
    final_kernel<<<NCN, 1024>>>((float*)d_out);
}

// round 7
// speedup vs baseline: 4.5650x; 1.3089x over previous
#include <cuda_runtime.h>
#include <cstdint>
#include <cstddef>

#define NCN    32      // 2*16 centroid matrices
#define NB     1024    // number of sampled indices
#define NBINS  2048    // batch size B (histogram bins)
#define NCHUNK 128     // b-chunks in main kernel grid
#define WPB    8       // warps per block (main kernel)
#define NMID   8       // mid-reduced chunk count
#define SSUM   3.0f    // sum of w_i/t_i for GL-2 on [0,1] (exactly 3)
#define NSIT   16      // Newton-Schulz sign iterations

// ---- scratch (static device globals; no allocation APIs) ----
__device__ float g_partial[NCHUNK * NCN * 1024];      // per-chunk partial sums
__device__ float g_partial2[NMID * NCN * 1024];       // mid-reduced partials
__device__ int   g_list[NB];                          // distinct xb values (ascending)
__device__ float g_cnt[NB];                           // multiplicity weights (0 = idle)

// Gauss-Legendre 2-node on [0,1]
#define T0   0.21132486540518713f
#define T1   0.78867513459481287f
#define WOT0 2.3660254037844384f
#define WOT1 0.6339745962155614f

// ---- packed f32x2 helpers ----
union f2u { float2 f; unsigned long long u; };
__device__ __forceinline__ float2 ffma2(float2 a, float2 b, float2 c) {
    f2u A, B, C, R; A.f = a; B.f = b; C.f = c;
    asm("fma.rn.f32x2 %0, %1, %2, %3;" : "=l"(R.u) : "l"(A.u), "l"(B.u), "l"(C.u));
    return R.f;
}
struct __align__(16) pf4 { float2 lo, hi; };

// 4x4 inverse via cofactors (1 divide, flat dependency depth)
__device__ __forceinline__ void inv4x4(const float* m, float* inv) {
    const float s0 = m[0]*m[5] - m[4]*m[1];
    const float s1 = m[0]*m[6] - m[4]*m[2];
    const float s2 = m[0]*m[7] - m[4]*m[3];
    const float s3 = m[1]*m[6] - m[5]*m[2];
    const float s4 = m[1]*m[7] - m[5]*m[3];
    const float s5 = m[2]*m[7] - m[6]*m[3];
    const float c5 = m[10]*m[15] - m[14]*m[11];
    const float c4 = m[9]*m[15]  - m[13]*m[11];
    const float c3 = m[9]*m[14]  - m[13]*m[10];
    const float c2 = m[8]*m[15]  - m[12]*m[11];
    const float c1 = m[8]*m[14]  - m[12]*m[10];
    const float c0 = m[8]*m[13]  - m[12]*m[9];
    const float det = s0*c5 - s1*c4 + s2*c3 + s3*c2 - s4*c1 + s5*c0;
    const float id = __fdividef(1.f, det);
    inv[0]  = ( m[5]*c5 - m[6]*c4 + m[7]*c3) * id;
    inv[1]  = (-m[1]*c5 + m[2]*c4 - m[3]*c3) * id;
    inv[2]  = ( m[13]*s5 - m[14]*s4 + m[15]*s3) * id;
    inv[3]  = (-m[9]*s5 + m[10]*s4 - m[11]*s3) * id;
    inv[4]  = (-m[4]*c5 + m[6]*c2 - m[7]*c1) * id;
    inv[5]  = ( m[0]*c5 - m[2]*c2 + m[3]*c1) * id;
    inv[6]  = (-m[12]*s5 + m[14]*s2 - m[15]*s1) * id;
    inv[7]  = ( m[8]*s5 - m[10]*s2 + m[11]*s1) * id;
    inv[8]  = ( m[4]*c4 - m[5]*c2 + m[7]*c0) * id;
    inv[9]  = (-m[0]*c4 + m[1]*c2 - m[3]*c0) * id;
    inv[10] = ( m[12]*s4 - m[13]*s2 + m[15]*s0) * id;
    inv[11] = (-m[8]*s4 + m[9]*s2 - m[11]*s0) * id;
    inv[12] = (-m[4]*c3 + m[5]*c1 - m[6]*c0) * id;
    inv[13] = ( m[0]*c3 - m[1]*c1 + m[2]*c0) * id;
    inv[14] = (-m[12]*s3 + m[13]*s1 - m[14]*s0) * id;
    inv[15] = ( m[8]*s3 - m[9]*s1 + m[10]*s0) * id;
}

// ============================================================================
// Dedup in one launch: smem histogram + ordered compaction (deterministic).
// ============================================================================
__global__ void dedup_kernel(const int* __restrict__ idx) {
    __shared__ int h[NBINS];
    __shared__ int s1[1024], s2[1024];
    const int t = threadIdx.x;
    h[t] = 0; h[t + 1024] = 0;
    g_list[t] = 0; g_cnt[t] = 0.f;
    __syncthreads();
    atomicAdd(&h[idx[t]], 1);
    __syncthreads();
    const int h0 = h[2 * t], h1 = h[2 * t + 1];
    const int p0 = h0 > 0, p1 = h1 > 0;
    s1[t] = p0 + p1;
    __syncthreads();
    int* src = s1; int* dst = s2;
    for (int off = 1; off < 1024; off <<= 1) {
        int v = src[t];
        if (t >= off) v += src[t - off];
        dst[t] = v;
        __syncthreads();
        int* tmp = src; src = dst; dst = tmp;
    }
    const int excl = src[t] - (p0 + p1);
    if (p0) { g_list[excl] = 2 * t;          g_cnt[excl] = (float)h0; }
    if (p1) { g_list[excl + p0] = 2 * t + 1; g_cnt[excl + p0] = (float)h1; }
}
__global__ void nodedup_kernel(const int* __restrict__ idx) {
    g_list[threadIdx.x] = idx[threadIdx.x];
    g_cnt[threadIdx.x] = 1.f;
}

// ============================================================================
// Main kernel: accumulate w*(wot0*inv(B0)+wot1*inv(B1)), B_nd = t_nd*X+(1-t_nd)*C.
// One warp per (slot, cn). Block-pivot (4x4) pivot-free Gauss-Jordan:
// 8 rounds/inverse, lane-local 4x4 pivot inversion, rank-4 packed-FMA update.
// ============================================================================
__global__ void __launch_bounds__(256, 3) main_kernel(const float* __restrict__ X,
                                                      const float* __restrict__ Cin) {
    __shared__ __align__(16) float sC[32 * 36];         // C rows (stride 36)
    __shared__ __align__(16) float sBuf[WPB][32 * 36];  // per-warp accumulator
    __shared__ __align__(16) float sBc[WPB][2][4 * 36]; // dbl-buffered 4-row panel
    const int tid = threadIdx.x, warp = tid >> 5, lane = tid & 31;
    const int cn = blockIdx.y;
    const int slot = blockIdx.x * WPB + warp;

    for (int k = tid; k < 1024; k += 256)
        sC[(k >> 5) * 36 + (k & 31)] = Cin[cn * 1024 + k];
    __syncthreads();

    float* bufrow = sBuf[warp] + lane * 36;
    pf4* br = (pf4*)bufrow;
    const float w = g_cnt[slot];

    if (w > 0.f) {
        const float* Xrow = X + (((size_t)g_list[slot] * NCN + cn) << 10) + (lane << 5);
        const pf4* crow = (const pf4*)(sC + lane * 36);
        const int myblk = lane >> 2, myr = lane & 3;

        #pragma unroll 1
        for (int nd = 0; nd < 2; nd++) {
            const float t = nd ? T1 : T0;
            const float omt = 1.f - t;
            const float2 t2 = make_float2(t, t);

            // B = t*X + (1-t)*C   (row `lane` in registers)
            float2 B2[16];
            #pragma unroll
            for (int q = 0; q < 8; q++) {
                const float4 xv = ((const float4*)Xrow)[q];
                const pf4 cv = crow[q];
                B2[2*q]   = ffma2(t2, make_float2(xv.x, xv.y),
                                  make_float2(omt * cv.lo.x, omt * cv.lo.y));
                B2[2*q+1] = ffma2(t2, make_float2(xv.z, xv.w),
                                  make_float2(omt * cv.hi.x, omt * cv.hi.y));
            }

            // block-pivot Gauss-Jordan inverse (8 rounds of 4 columns)
            #pragma unroll
            for (int kb = 0; kb < 8; kb++) {
                float* bc = sBc[warp][kb & 1];
                if (myblk == kb) {
                    pf4* bp = (pf4*)(bc + myr * 36);
                    #pragma unroll
                    for (int q = 0; q < 8; q++) {
                        pf4 v; v.lo = B2[2*q]; v.hi = B2[2*q+1];
                        bp[q] = v;
                    }
                }
                __syncwarp();
                // pivot block P = rows 0..3, cols 4kb..4kb+3
                float P[16];
                #pragma unroll
                for (int r = 0; r < 4; r++) {
                    const float4 pv = *(const float4*)(bc + r * 36 + 4 * kb);
                    P[4*r] = pv.x; P[4*r+1] = pv.y; P[4*r+2] = pv.z; P[4*r+3] = pv.w;
                }
                float Pi[16];
                inv4x4(P, Pi);
                // own block-column values minus identity (unified owner trick)
                const float cd0 = B2[2*kb].x   - ((lane == 4*kb + 0) ? 1.f : 0.f);
                const float cd1 = B2[2*kb].y   - ((lane == 4*kb + 1) ? 1.f : 0.f);
                const float cd2 = B2[2*kb+1].x - ((lane == 4*kb + 2) ? 1.f : 0.f);
                const float cd3 = B2[2*kb+1].y - ((lane == 4*kb + 3) ? 1.f : 0.f);
                const float F0 = cd0*Pi[0] + cd1*Pi[4] + cd2*Pi[8]  + cd3*Pi[12];
                const float F1 = cd0*Pi[1] + cd1*Pi[5] + cd2*Pi[9]  + cd3*Pi[13];
                const float F2 = cd0*Pi[2] + cd1*Pi[6] + cd2*Pi[10] + cd3*Pi[14];
                const float F3 = cd0*Pi[3] + cd1*Pi[7] + cd2*Pi[11] + cd3*Pi[15];
                const float2 nF0 = make_float2(-F0, -F0), nF1 = make_float2(-F1, -F1);
                const float2 nF2 = make_float2(-F2, -F2), nF3 = make_float2(-F3, -F3);
                const pf4* r0 = (const pf4*)(bc);
                const pf4* r1 = (const pf4*)(bc + 36);
                const pf4* r2 = (const pf4*)(bc + 72);
                const pf4* r3 = (const pf4*)(bc + 108);
                #pragma unroll
                for (int q = 0; q < 8; q++) {
                    const pf4 v0 = r0[q], v1 = r1[q], v2 = r2[q], v3 = r3[q];
                    B2[2*q]   = ffma2(nF0, v0.lo, ffma2(nF1, v1.lo,
                                ffma2(nF2, v2.lo, ffma2(nF3, v3.lo, B2[2*q]))));
                    B2[2*q+1] = ffma2(nF0, v0.hi, ffma2(nF1, v1.hi,
                                ffma2(nF2, v2.hi, ffma2(nF3, v3.hi, B2[2*q+1]))));
                }
                // block-column fixup: delta - F  (owner rows get Pi rows, others -F)
                B2[2*kb]   = make_float2(((lane == 4*kb + 0) ? 1.f : 0.f) - F0,
                                         ((lane == 4*kb + 1) ? 1.f : 0.f) - F1);
                B2[2*kb+1] = make_float2(((lane == 4*kb + 2) ? 1.f : 0.f) - F2,
                                         ((lane == 4*kb + 3) ? 1.f : 0.f) - F3);
            }

            // accumulate (w*wot)*Binv into own sBuf row
            const float sw = w * (nd ? WOT1 : WOT0);
            const float2 sw2 = make_float2(sw, sw);
            if (nd == 0) {
                #pragma unroll
                for (int q = 0; q < 8; q++) {
                    pf4 v;
                    v.lo = make_float2(sw * B2[2*q].x, sw * B2[2*q].y);
                    v.hi = make_float2(sw * B2[2*q+1].x, sw * B2[2*q+1].y);
                    br[q] = v;
                }
            } else {
                #pragma unroll
                for (int q = 0; q < 8; q++) {
                    pf4 v = br[q];
                    v.lo = ffma2(sw2, B2[2*q], v.lo);
                    v.hi = ffma2(sw2, B2[2*q+1], v.hi);
                    br[q] = v;
                }
            }
        }
    } else {
        pf4 z; z.lo = make_float2(0.f, 0.f); z.hi = z.lo;
        #pragma unroll
        for (int q = 0; q < 8; q++) br[q] = z;
    }
    __syncthreads();

    // deterministic block reduction over the 8 warps -> partial buffer
    float* outp = g_partial + ((size_t)blockIdx.x * NCN + cn) * 1024;
    for (int e = tid; e < 1024; e += 256) {
        const int r = e >> 5, cc = e & 31;
        float s = 0.f;
        #pragma unroll
        for (int wp = 0; wp < WPB; wp++) s += sBuf[wp][r * 36 + cc];
        outp[e] = s;
    }
}

// ============================================================================
// Mid-reduction: collapse 128 chunks -> 8, at full-chip DRAM bandwidth.
// grid(NCN, NMID), block 1024. Deterministic fixed-order sums.
// ============================================================================
__global__ void midreduce_kernel() {
    const int cn = blockIdx.x, g = blockIdx.y, tid = threadIdx.x;
    float s = 0.f;
    const float* pp = g_partial + ((size_t)(g * (NCHUNK / NMID)) * NCN + cn) * 1024 + tid;
    #pragma unroll
    for (int c = 0; c < NCHUNK / NMID; c++) s += pp[(size_t)c * NCN * 1024];
    g_partial2[((size_t)g * NCN + cn) * 1024 + tid] = s;
}

// ============================================================================
// Final kernel (block = 1024, thread per element). Includes former prep:
//   Cp   = sqrtm(C) via Newton-Schulz
//   Abar = reduce(g_partial2)/NB
//   L    = eta*(SSUM*I - Cp*Abar*Cp)
//   S    = sgn(L) via Newton-Schulz;  E = S*cosh(L) + sinh(L)
//   out  = Cp * E * Cp
// ============================================================================
__global__ void final_kernel(const float* __restrict__ C, float* __restrict__ out) {
    __shared__ float m0[32*33], m1[32*33], m2[32*33], m3[32*33], m4[32*33], m5[32*33];
    __shared__ float sRed[32];
    __shared__ float sScal;
    const int cn = blockIdx.x, tid = threadIdx.x;
    const int i = tid >> 5, j = tid & 31, ro = i * 33;

    const float cij = C[cn * 1024 + tid];
    // trace mean
    {
        float v = (i == j) ? cij : 0.f;
        #pragma unroll
        for (int o = 16; o > 0; o >>= 1) v += __shfl_xor_sync(0xffffffffu, v, o);
        if (j == 0) sRed[i] = v;
    }
    __syncthreads();
    if (tid < 32) {
        float v = sRed[tid];
        #pragma unroll
        for (int o = 16; o > 0; o >>= 1) v += __shfl_xor_sync(0xffffffffu, v, o);
        if (tid == 0) sScal = v * (1.f / 32.f);
    }
    __syncthreads();
    const float c = sScal, invc = 1.f / c;

    // Newton-Schulz coupled sqrt on C/c
    m1[ro + j] = cij * invc;
    m2[ro + j] = (i == j) ? 1.f : 0.f;
    __syncthreads();
    float *Y = m1, *Z = m2, *Pm = m3, *Ya = m4, *Za = m5;
    for (int it = 0; it < 6; it++) {
        float a = 0.f;
        #pragma unroll
        for (int k = 0; k < 32; k++) a = fmaf(Z[ro + k], Y[k * 33 + j], a);
        Pm[ro + j] = ((i == j) ? 1.5f : 0.f) - 0.5f * a;
        __syncthreads();
        float a1 = 0.f, a2 = 0.f;
        #pragma unroll
        for (int k = 0; k < 32; k++) {
            a1 = fmaf(Y[ro + k], Pm[k * 33 + j], a1);
            a2 = fmaf(Pm[ro + k], Z[k * 33 + j], a2);
        }
        Ya[ro + j] = a1; Za[ro + j] = a2;
        __syncthreads();
        float* ty = Y; float* tz = Z; float* tp = Pm;
        Y = Ya; Z = Za; Pm = ty; Ya = tz; Za = tp;
    }
    // Cp = Y * sqrt(c) -> m0 ; {Y,Z,Pm,Ya,Za} = perm of {m1..m5} become scratch
    float* sCp = m0;
    sCp[ro + j] = Y[ro + j] * sqrtf(c);
    float* sT = Y; float* sU = Z; float* sL = Pm; float* sSa = Ya; float* sSb = Za;

    // Abar from mid-reduced partials -> sT
    {
        float s = 0.f;
        #pragma unroll
        for (int g = 0; g < NMID; g++)
            s += g_partial2[((size_t)g * NCN + cn) * 1024 + tid];
        sT[ro + j] = s * (1.f / 1024.f);
    }
    __syncthreads();

    // U = Abar * Cp -> sU
    {
        float s = 0.f;
        #pragma unroll
        for (int k = 0; k < 32; k++) s = fmaf(sT[ro + k], sCp[k * 33 + j], s);
        sU[ro + j] = s;
    }
    __syncthreads();

    // L = eta*(SSUM*I - Cp*U) -> sL ; Frobenius norm
    float lv;
    {
        float s = 0.f;
        #pragma unroll
        for (int k = 0; k < 32; k++) s = fmaf(sCp[ro + k], sU[k * 33 + j], s);
        lv = 0.01f * (((i == j) ? SSUM : 0.f) - s);
        sL[ro + j] = lv;
    }
    {
        float v = lv * lv;
        #pragma unroll
        for (int o = 16; o > 0; o >>= 1) v += __shfl_xor_sync(0xffffffffu, v, o);
        if (j == 0) sRed[i] = v;
    }
    __syncthreads();
    if (tid < 32) {
        float v = sRed[tid];
        #pragma unroll
        for (int o = 16; o > 0; o >>= 1) v += __shfl_xor_sync(0xffffffffu, v, o);
        if (tid == 0) sScal = rsqrtf(v + 1e-30f);
    }
    __syncthreads();

    // S0 = L / ||L||_F
    sSa[ro + j] = lv * sScal;
    __syncthreads();

    // Newton-Schulz sign: S <- 1.5S - 0.5 S^3
    float* S = sSa; float* Sn = sSb;
    for (int it = 0; it < NSIT; it++) {
        {
            float s = 0.f;
            #pragma unroll
            for (int k = 0; k < 32; k++) s = fmaf(S[ro + k], S[k * 33 + j], s);
            sT[ro + j] = s;
        }
        __syncthreads();
        {
            float s = 0.f;
            #pragma unroll
            for (int k = 0; k < 32; k++) s = fmaf(S[ro + k], sT[k * 33 + j], s);
            Sn[ro + j] = 1.5f * S[ro + j] - 0.5f * s;
        }
        __syncthreads();
        float* tmp = S; S = Sn; Sn = tmp;
    }

    // P2 = L*L -> sT
    {
        float s = 0.f;
        #pragma unroll
        for (int k = 0; k < 32; k++) s = fmaf(sL[ro + k], sL[k * 33 + j], s);
        sT[ro + j] = s;
    }
    __syncthreads();
    // sinh(L) ~= L + L*P2/6 -> sU
    {
        float s = 0.f;
        #pragma unroll
        for (int k = 0; k < 32; k++) s = fmaf(sL[ro + k], sT[k * 33 + j], s);
        sU[ro + j] = fmaf(s, (1.f / 6.f), sL[ro + j]);
    }
    __syncthreads();
    // cosh(L) ~= I + P2/2 + P2*P2/24 -> Sn
    {
        float s = 0.f;
        #pragma unroll
        for (int k = 0; k < 32; k++) s = fmaf(sT[ro + k], sT[k * 33 + j], s);
        Sn[ro + j] = ((i == j) ? 1.f : 0.f) + 0.5f * sT[ro + j] + s * (1.f / 24.f);
    }
    __syncthreads();
    // E = S*cosh + sinh -> sT
    {
        float s = 0.f;
        #pragma unroll
        for (int k = 0; k < 32; k++) s = fmaf(S[ro + k], Sn[k * 33 + j], s);
        sT[ro + j] = s + sU[ro + j];
    }
    __syncthreads();
    // V = E * Cp -> sU
    {
        float s = 0.f;
        #pragma unroll
        for (int k = 0; k < 32; k++) s = fmaf(sT[ro + k], sCp[k * 33 + j], s);
        sU[ro + j] = s;
    }
    __syncthreads();
    // out = Cp * V
    {
        float s = 0.f;
        #pragma unroll
        for (int k = 0; k < 32; k++) s = fmaf(sCp[ro + k], sU[k * 33 + j], s);
        out[cn * 1024 + tid] = s;
    }
}

// ============================================================================
extern "C" void kernel_launch(void* const* d_in, const int* in_sizes, int n_in,
                              void* d_out, int out_size) {
    const float* X = nullptr;
    const float* C = nullptr;
    const int* idx = nullptr;
    int xElems = 0;
    for (int i = 0; i < n_in; i++) {
        if (in_sizes[i] == NB) idx = (const int*)d_in[i];
        else if (in_sizes[i] == NCN * 1024) C = (const float*)d_in[i];
        else { X = (const float*)d_in[i]; xElems = in_sizes[i]; }
    }
    const int batch = xElems / (NCN * 1024);

    if (batch == NBINS) {
        dedup_kernel<<<1, 1024>>>(idx);
    } else {
        nodedup_kernel<<<1, NB>>>(idx);
    }
    dim3 grid(NCHUNK, NCN);
    main_kernel<<<grid, 256>>>(X, C);
    dim3 mgrid(NCN, NMID);
    midreduce_kernel<<<mgrid, 1024>>>();
    final_kernel<<<NCN, 1024>>>(C, (float*)d_out);
}

// round 8
// speedup vs baseline: 5.4237x; 1.1881x over previous
#include <cuda_runtime.h>
#include <cstdint>
#include <cstddef>

#define NCN    32      // 2*16 centroid matrices
#define NB     1024    // number of sampled indices
#define NBINS  2048    // batch size B (histogram bins)
#define NCHUNK 128     // b-chunks in main kernel grid
#define WPB    8       // warps per block (main kernel)
#define NMID   8       // mid-reduced chunk count
#define SSUM   3.0f    // sum of w_i/t_i for GL-2 on [0,1] (exactly 3)
#define ST     36      // padded row stride for final-kernel matrices

// polar-express quintic sign coefficients
#define PE_A   3.4445f
#define PE_B  (-4.7750f)
#define PE_C   2.0315f
#define NPE    4       // quintic iterations
#define NNS    6       // Newton-Schulz refinement iterations

// ---- scratch (static device globals; no allocation APIs) ----
__device__ float g_partial[NCHUNK * NCN * 1024];      // per-chunk partial sums
__device__ float g_partial2[NMID * NCN * 1024];       // mid-reduced partials
__device__ int   g_list[NB];                          // distinct xb values (ascending)
__device__ float g_cnt[NB];                           // multiplicity weights (0 = idle)

// Gauss-Legendre 2-node on [0,1]
#define T0   0.21132486540518713f
#define T1   0.78867513459481287f
#define WOT0 2.3660254037844384f
#define WOT1 0.6339745962155614f

// ---- packed f32x2 helpers ----
union f2u { float2 f; unsigned long long u; };
__device__ __forceinline__ float2 ffma2(float2 a, float2 b, float2 c) {
    f2u A, B, C, R; A.f = a; B.f = b; C.f = c;
    asm("fma.rn.f32x2 %0, %1, %2, %3;" : "=l"(R.u) : "l"(A.u), "l"(B.u), "l"(C.u));
    return R.f;
}
struct __align__(16) pf4 { float2 lo, hi; };

__device__ __forceinline__ float f4c(const float4 v, int c) {
    return c == 0 ? v.x : c == 1 ? v.y : c == 2 ? v.z : v.w;
}

// 4x4 adjugate + reciprocal determinant (divide deferred to caller)
__device__ __forceinline__ float adj4x4(const float* m, float* adj) {
    const float s0 = m[0]*m[5] - m[4]*m[1];
    const float s1 = m[0]*m[6] - m[4]*m[2];
    const float s2 = m[0]*m[7] - m[4]*m[3];
    const float s3 = m[1]*m[6] - m[5]*m[2];
    const float s4 = m[1]*m[7] - m[5]*m[3];
    const float s5 = m[2]*m[7] - m[6]*m[3];
    const float c5 = m[10]*m[15] - m[14]*m[11];
    const float c4 = m[9]*m[15]  - m[13]*m[11];
    const float c3 = m[9]*m[14]  - m[13]*m[10];
    const float c2 = m[8]*m[15]  - m[12]*m[11];
    const float c1 = m[8]*m[14]  - m[12]*m[10];
    const float c0 = m[8]*m[13]  - m[12]*m[9];
    const float det = s0*c5 - s1*c4 + s2*c3 + s3*c2 - s4*c1 + s5*c0;
    adj[0]  =  m[5]*c5 - m[6]*c4 + m[7]*c3;
    adj[1]  = -m[1]*c5 + m[2]*c4 - m[3]*c3;
    adj[2]  =  m[13]*s5 - m[14]*s4 + m[15]*s3;
    adj[3]  = -m[9]*s5 + m[10]*s4 - m[11]*s3;
    adj[4]  = -m[4]*c5 + m[6]*c2 - m[7]*c1;
    adj[5]  =  m[0]*c5 - m[2]*c2 + m[3]*c1;
    adj[6]  = -m[12]*s5 + m[14]*s2 - m[15]*s1;
    adj[7]  =  m[8]*s5 - m[10]*s2 + m[11]*s1;
    adj[8]  =  m[4]*c4 - m[5]*c2 + m[7]*c0;
    adj[9]  = -m[0]*c4 + m[1]*c2 - m[3]*c0;
    adj[10] =  m[12]*s4 - m[13]*s2 + m[15]*s0;
    adj[11] = -m[8]*s4 + m[9]*s2 - m[11]*s0;
    adj[12] = -m[4]*c3 + m[5]*c1 - m[6]*c0;
    adj[13] =  m[0]*c3 - m[1]*c1 + m[2]*c0;
    adj[14] = -m[12]*s3 + m[13]*s1 - m[14]*s0;
    adj[15] =  m[8]*s3 - m[9]*s1 + m[10]*s0;
    return __fdividef(1.f, det);
}

// ============================================================================
// Dedup in one launch: smem histogram + ordered compaction (deterministic).
// ============================================================================
__global__ void dedup_kernel(const int* __restrict__ idx) {
    __shared__ int h[NBINS];
    __shared__ int s1[1024], s2[1024];
    const int t = threadIdx.x;
    h[t] = 0; h[t + 1024] = 0;
    g_list[t] = 0; g_cnt[t] = 0.f;
    __syncthreads();
    atomicAdd(&h[idx[t]], 1);
    __syncthreads();
    const int h0 = h[2 * t], h1 = h[2 * t + 1];
    const int p0 = h0 > 0, p1 = h1 > 0;
    s1[t] = p0 + p1;
    __syncthreads();
    int* src = s1; int* dst = s2;
    for (int off = 1; off < 1024; off <<= 1) {
        int v = src[t];
        if (t >= off) v += src[t - off];
        dst[t] = v;
        __syncthreads();
        int* tmp = src; src = dst; dst = tmp;
    }
    const int excl = src[t] - (p0 + p1);
    if (p0) { g_list[excl] = 2 * t;          g_cnt[excl] = (float)h0; }
    if (p1) { g_list[excl + p0] = 2 * t + 1; g_cnt[excl + p0] = (float)h1; }
}
__global__ void nodedup_kernel(const int* __restrict__ idx) {
    g_list[threadIdx.x] = idx[threadIdx.x];
    g_cnt[threadIdx.x] = 1.f;
}

// ============================================================================
// Main kernel: accumulate w*(wot0*inv(B0)+wot1*inv(B1)), B_nd = t_nd*X+(1-t_nd)*C.
// One warp per (slot, cn). Block-pivot (4x4) pivot-free Gauss-Jordan:
// 8 rounds/inverse, lane-local adjugate pivot inversion, rank-4 packed update.
// ============================================================================
__global__ void __launch_bounds__(256, 3) main_kernel(const float* __restrict__ X,
                                                      const float* __restrict__ Cin) {
    __shared__ __align__(16) float sC[32 * 36];         // C rows (stride 36)
    __shared__ __align__(16) float sBuf[WPB][32 * 36];  // per-warp accumulator
    __shared__ __align__(16) float sBc[WPB][2][4 * 36]; // dbl-buffered 4-row panel
    const int tid = threadIdx.x, warp = tid >> 5, lane = tid & 31;
    const int cn = blockIdx.y;
    const int slot = blockIdx.x * WPB + warp;

    for (int k = tid; k < 1024; k += 256)
        sC[(k >> 5) * 36 + (k & 31)] = Cin[cn * 1024 + k];
    __syncthreads();

    float* bufrow = sBuf[warp] + lane * 36;
    pf4* br = (pf4*)bufrow;
    const float w = g_cnt[slot];

    if (w > 0.f) {
        const float* Xrow = X + (((size_t)g_list[slot] * NCN + cn) << 10) + (lane << 5);
        const pf4* crow = (const pf4*)(sC + lane * 36);
        const int myblk = lane >> 2, myr = lane & 3;

        #pragma unroll 1
        for (int nd = 0; nd < 2; nd++) {
            const float t = nd ? T1 : T0;
            const float omt = 1.f - t;
            const float2 t2 = make_float2(t, t);

            // B = t*X + (1-t)*C   (row `lane` in registers)
            float2 B2[16];
            #pragma unroll
            for (int q = 0; q < 8; q++) {
                const float4 xv = ((const float4*)Xrow)[q];
                const pf4 cv = crow[q];
                B2[2*q]   = ffma2(t2, make_float2(xv.x, xv.y),
                                  make_float2(omt * cv.lo.x, omt * cv.lo.y));
                B2[2*q+1] = ffma2(t2, make_float2(xv.z, xv.w),
                                  make_float2(omt * cv.hi.x, omt * cv.hi.y));
            }

            // block-pivot Gauss-Jordan inverse (8 rounds of 4 columns)
            #pragma unroll
            for (int kb = 0; kb < 8; kb++) {
                float* bc = sBc[warp][kb & 1];
                if (myblk == kb) {
                    pf4* bp = (pf4*)(bc + myr * 36);
                    #pragma unroll
                    for (int q = 0; q < 8; q++) {
                        pf4 v; v.lo = B2[2*q]; v.hi = B2[2*q+1];
                        bp[q] = v;
                    }
                }
                __syncwarp();
                // pivot block P = rows 0..3, cols 4kb..4kb+3
                float P[16];
                #pragma unroll
                for (int r = 0; r < 4; r++) {
                    const float4 pv = *(const float4*)(bc + r * 36 + 4 * kb);
                    P[4*r] = pv.x; P[4*r+1] = pv.y; P[4*r+2] = pv.z; P[4*r+3] = pv.w;
                }
                float Aj[16];
                const float id = adj4x4(P, Aj);
                // own block-column values minus identity (unified owner trick)
                const float cd0 = B2[2*kb].x   - ((lane == 4*kb + 0) ? 1.f : 0.f);
                const float cd1 = B2[2*kb].y   - ((lane == 4*kb + 1) ? 1.f : 0.f);
                const float cd2 = B2[2*kb+1].x - ((lane == 4*kb + 2) ? 1.f : 0.f);
                const float cd3 = B2[2*kb+1].y - ((lane == 4*kb + 3) ? 1.f : 0.f);
                const float F0 = (cd0*Aj[0] + cd1*Aj[4] + cd2*Aj[8]  + cd3*Aj[12]) * id;
                const float F1 = (cd0*Aj[1] + cd1*Aj[5] + cd2*Aj[9]  + cd3*Aj[13]) * id;
                const float F2 = (cd0*Aj[2] + cd1*Aj[6] + cd2*Aj[10] + cd3*Aj[14]) * id;
                const float F3 = (cd0*Aj[3] + cd1*Aj[7] + cd2*Aj[11] + cd3*Aj[15]) * id;
                const float2 nF0 = make_float2(-F0, -F0), nF1 = make_float2(-F1, -F1);
                const float2 nF2 = make_float2(-F2, -F2), nF3 = make_float2(-F3, -F3);
                const pf4* r0 = (const pf4*)(bc);
                const pf4* r1 = (const pf4*)(bc + 36);
                const pf4* r2 = (const pf4*)(bc + 72);
                const pf4* r3 = (const pf4*)(bc + 108);
                #pragma unroll
                for (int q = 0; q < 8; q++) {
                    const pf4 v0 = r0[q], v1 = r1[q], v2 = r2[q], v3 = r3[q];
                    B2[2*q]   = ffma2(nF0, v0.lo, ffma2(nF1, v1.lo,
                                ffma2(nF2, v2.lo, ffma2(nF3, v3.lo, B2[2*q]))));
                    B2[2*q+1] = ffma2(nF0, v0.hi, ffma2(nF1, v1.hi,
                                ffma2(nF2, v2.hi, ffma2(nF3, v3.hi, B2[2*q+1]))));
                }
                // block-column fixup: delta - F
                B2[2*kb]   = make_float2(((lane == 4*kb + 0) ? 1.f : 0.f) - F0,
                                         ((lane == 4*kb + 1) ? 1.f : 0.f) - F1);
                B2[2*kb+1] = make_float2(((lane == 4*kb + 2) ? 1.f : 0.f) - F2,
                                         ((lane == 4*kb + 3) ? 1.f : 0.f) - F3);
            }

            // accumulate (w*wot)*Binv into own sBuf row
            const float sw = w * (nd ? WOT1 : WOT0);
            const float2 sw2 = make_float2(sw, sw);
            if (nd == 0) {
                #pragma unroll
                for (int q = 0; q < 8; q++) {
                    pf4 v;
                    v.lo = make_float2(sw * B2[2*q].x, sw * B2[2*q].y);
                    v.hi = make_float2(sw * B2[2*q+1].x, sw * B2[2*q+1].y);
                    br[q] = v;
                }
            } else {
                #pragma unroll
                for (int q = 0; q < 8; q++) {
                    pf4 v = br[q];
                    v.lo = ffma2(sw2, B2[2*q], v.lo);
                    v.hi = ffma2(sw2, B2[2*q+1], v.hi);
                    br[q] = v;
                }
            }
        }
    } else {
        pf4 z; z.lo = make_float2(0.f, 0.f); z.hi = z.lo;
        #pragma unroll
        for (int q = 0; q < 8; q++) br[q] = z;
    }
    __syncthreads();

    // deterministic block reduction over the 8 warps -> partial buffer
    float* outp = g_partial + ((size_t)blockIdx.x * NCN + cn) * 1024;
    for (int e = tid; e < 1024; e += 256) {
        const int r = e >> 5, cc = e & 31;
        float s = 0.f;
        #pragma unroll
        for (int wp = 0; wp < WPB; wp++) s += sBuf[wp][r * 36 + cc];
        outp[e] = s;
    }
}

// ============================================================================
// Mid-reduction: collapse 128 chunks -> 8, at full-chip DRAM bandwidth.
// ============================================================================
__global__ void midreduce_kernel() {
    const int cn = blockIdx.x, g = blockIdx.y, tid = threadIdx.x;
    float s = 0.f;
    const float* pp = g_partial + ((size_t)(g * (NCHUNK / NMID)) * NCN + cn) * 1024 + tid;
    #pragma unroll
    for (int c = 0; c < NCHUNK / NMID; c++) s += pp[(size_t)c * NCN * 1024];
    g_partial2[((size_t)g * NCN + cn) * 1024 + tid] = s;
}

// ============================================================================
// Final kernel: 256 threads, register-tiled matmul passes (warp w owns rows
// 4w..4w+3, lane = column). One __syncthreads per pass.
//   Cp = sqrtm(C) (NS); L = eta*(SSUM*I - Cp*Abar*Cp)
//   S = sgn(L) via 4x quintic polar-express + 6x NS refine
//   E = S*cosh(L) + sinh(L);  out = Cp * E * Cp
// ============================================================================

// acc[r] += A(r0+r, :) * B(:, j)   A rows via LDS.128 broadcast, B cols scalar
__device__ __forceinline__ void mm32(const float* __restrict__ A,
                                     const float* __restrict__ B,
                                     float* acc, int r0, int j) {
    #pragma unroll
    for (int kb = 0; kb < 8; kb++) {
        const float4 a0 = *(const float4*)(A + (r0+0)*ST + 4*kb);
        const float4 a1 = *(const float4*)(A + (r0+1)*ST + 4*kb);
        const float4 a2 = *(const float4*)(A + (r0+2)*ST + 4*kb);
        const float4 a3 = *(const float4*)(A + (r0+3)*ST + 4*kb);
        #pragma unroll
        for (int t = 0; t < 4; t++) {
            const float bk = B[(4*kb + t)*ST + j];
            acc[0] = fmaf(f4c(a0, t), bk, acc[0]);
            acc[1] = fmaf(f4c(a1, t), bk, acc[1]);
            acc[2] = fmaf(f4c(a2, t), bk, acc[2]);
            acc[3] = fmaf(f4c(a3, t), bk, acc[3]);
        }
    }
}

__global__ void __launch_bounds__(256) final_kernel(const float* __restrict__ C,
                                                    float* __restrict__ out) {
    __shared__ __align__(16) float sCp[32*ST], sL[32*ST];
    __shared__ __align__(16) float b1[32*ST], b2[32*ST], b3[32*ST], b4[32*ST], b5[32*ST];
    __shared__ float sRed[8];
    __shared__ float sScal;
    const int cn = blockIdx.x, tid = threadIdx.x;
    const int warp = tid >> 5, j = tid & 31, r0 = warp << 2;

    // load C rows; trace
    float cv[4];
    #pragma unroll
    for (int r = 0; r < 4; r++) cv[r] = C[cn * 1024 + (r0 + r) * 32 + j];
    {
        float v = 0.f;
        #pragma unroll
        for (int r = 0; r < 4; r++) if (j == r0 + r) v += cv[r];
        #pragma unroll
        for (int o = 16; o > 0; o >>= 1) v += __shfl_xor_sync(0xffffffffu, v, o);
        if (j == 0) sRed[warp] = v;
    }
    __syncthreads();
    if (tid == 0) {
        float s = 0.f;
        #pragma unroll
        for (int r = 0; r < 8; r++) s += sRed[r];
        sScal = s * (1.f / 32.f);
    }
    __syncthreads();
    const float c = sScal, invc = 1.f / c;

    // NS coupled sqrt on C/c: Y in b1, Z in b2
    #pragma unroll
    for (int r = 0; r < 4; r++) {
        b1[(r0 + r) * ST + j] = cv[r] * invc;
        b2[(r0 + r) * ST + j] = (r0 + r == j) ? 1.f : 0.f;
    }
    __syncthreads();
    float *Y = b1, *Z = b2, *Pm = b3, *Ya = b4, *Za = b5;
    for (int it = 0; it < 6; it++) {
        float acc[4] = {0.f, 0.f, 0.f, 0.f};
        mm32(Z, Y, acc, r0, j);
        #pragma unroll
        for (int r = 0; r < 4; r++)
            Pm[(r0 + r) * ST + j] = ((r0 + r == j) ? 1.5f : 0.f) - 0.5f * acc[r];
        __syncthreads();
        float a1[4] = {0.f, 0.f, 0.f, 0.f}, a2[4] = {0.f, 0.f, 0.f, 0.f};
        mm32(Y, Pm, a1, r0, j);
        mm32(Pm, Z, a2, r0, j);
        #pragma unroll
        for (int r = 0; r < 4; r++) {
            Ya[(r0 + r) * ST + j] = a1[r];
            Za[(r0 + r) * ST + j] = a2[r];
        }
        __syncthreads();
        float* t1 = Y; float* t2 = Z;
        Y = Ya; Z = Za; Ya = t1; Za = t2;
    }
    // Cp = Y * sqrt(c)
    const float sc = sqrtf(c);
    #pragma unroll
    for (int r = 0; r < 4; r++) sCp[(r0 + r) * ST + j] = Y[(r0 + r) * ST + j] * sc;
    __syncthreads();
    // all of b1..b5 now scratch
    float *S = b1, *Sn = b2, *Ta = b3, *Tb = b4, *Tc = b5;

    // Abar -> Ta
    #pragma unroll
    for (int r = 0; r < 4; r++) {
        float s = 0.f;
        #pragma unroll
        for (int g = 0; g < NMID; g++)
            s += g_partial2[((size_t)g * NCN + cn) * 1024 + (r0 + r) * 32 + j];
        Ta[(r0 + r) * ST + j] = s * (1.f / 1024.f);
    }
    __syncthreads();
    // U = Abar * Cp -> Tb
    {
        float acc[4] = {0.f, 0.f, 0.f, 0.f};
        mm32(Ta, sCp, acc, r0, j);
        #pragma unroll
        for (int r = 0; r < 4; r++) Tb[(r0 + r) * ST + j] = acc[r];
    }
    __syncthreads();
    // L = eta*(SSUM*I - Cp*U) -> sL ; Frobenius norm
    {
        float acc[4] = {0.f, 0.f, 0.f, 0.f};
        mm32(sCp, Tb, acc, r0, j);
        float fr = 0.f;
        #pragma unroll
        for (int r = 0; r < 4; r++) {
            const float lv = 0.01f * (((r0 + r == j) ? SSUM : 0.f) - acc[r]);
            sL[(r0 + r) * ST + j] = lv;
            fr = fmaf(lv, lv, fr);
        }
        #pragma unroll
        for (int o = 16; o > 0; o >>= 1) fr += __shfl_xor_sync(0xffffffffu, fr, o);
        if (j == 0) sRed[warp] = fr;
    }
    __syncthreads();
    if (tid == 0) {
        float s = 0.f;
        #pragma unroll
        for (int r = 0; r < 8; r++) s += sRed[r];
        sScal = rsqrtf(s + 1e-30f);
    }
    __syncthreads();
    // S0 = L / ||L||_F
    {
        const float ia = sScal;
        #pragma unroll
        for (int r = 0; r < 4; r++) S[(r0 + r) * ST + j] = sL[(r0 + r) * ST + j] * ia;
    }
    __syncthreads();

    // quintic polar-express iterations: S <- PE_A*S + PE_B*S^3 + PE_C*S^5
    for (int it = 0; it < NPE; it++) {
        float acc[4] = {0.f, 0.f, 0.f, 0.f};
        mm32(S, S, acc, r0, j);                 // T = S^2
        #pragma unroll
        for (int r = 0; r < 4; r++) Ta[(r0 + r) * ST + j] = acc[r];
        __syncthreads();
        float ac2[4] = {0.f, 0.f, 0.f, 0.f};
        mm32(Ta, Ta, ac2, r0, j);               // T2 = T^2
        #pragma unroll
        for (int r = 0; r < 4; r++)
            Tb[(r0 + r) * ST + j] = ((r0 + r == j) ? PE_A : 0.f)
                                  + PE_B * Ta[(r0 + r) * ST + j] + PE_C * ac2[r];
        __syncthreads();
        float ac3[4] = {0.f, 0.f, 0.f, 0.f};
        mm32(S, Tb, ac3, r0, j);                // S' = S * P
        #pragma unroll
        for (int r = 0; r < 4; r++) Sn[(r0 + r) * ST + j] = ac3[r];
        __syncthreads();
        float* t = S; S = Sn; Sn = t;
    }
    // NS refinement: S <- 1.5S - 0.5 S^3
    for (int it = 0; it < NNS; it++) {
        float acc[4] = {0.f, 0.f, 0.f, 0.f};
        mm32(S, S, acc, r0, j);
        #pragma unroll
        for (int r = 0; r < 4; r++) Ta[(r0 + r) * ST + j] = acc[r];
        __syncthreads();
        float ac2[4] = {0.f, 0.f, 0.f, 0.f};
        mm32(S, Ta, ac2, r0, j);
        #pragma unroll
        for (int r = 0; r < 4; r++)
            Sn[(r0 + r) * ST + j] = 1.5f * S[(r0 + r) * ST + j] - 0.5f * ac2[r];
        __syncthreads();
        float* t = S; S = Sn; Sn = t;
    }

    // P2 = L*L -> Ta
    {
        float acc[4] = {0.f, 0.f, 0.f, 0.f};
        mm32(sL, sL, acc, r0, j);
        #pragma unroll
        for (int r = 0; r < 4; r++) Ta[(r0 + r) * ST + j] = acc[r];
    }
    __syncthreads();
    // sinh(L) ~= L + L*P2/6 -> Tb
    {
        float acc[4] = {0.f, 0.f, 0.f, 0.f};
        mm32(sL, Ta, acc, r0, j);
        #pragma unroll
        for (int r = 0; r < 4; r++)
            Tb[(r0 + r) * ST + j] = fmaf(acc[r], (1.f / 6.f), sL[(r0 + r) * ST + j]);
    }
    __syncthreads();
    // cosh(L) ~= I + P2/2 + P2*P2/24 -> Tc
    {
        float acc[4] = {0.f, 0.f, 0.f, 0.f};
        mm32(Ta, Ta, acc, r0, j);
        #pragma unroll
        for (int r = 0; r < 4; r++)
            Tc[(r0 + r) * ST + j] = ((r0 + r == j) ? 1.f : 0.f)
                                  + 0.5f * Ta[(r0 + r) * ST + j] + acc[r] * (1.f / 24.f);
    }
    __syncthreads();
    // E = S*cosh + sinh -> Ta
    {
        float acc[4] = {0.f, 0.f, 0.f, 0.f};
        mm32(S, Tc, acc, r0, j);
        #pragma unroll
        for (int r = 0; r < 4; r++)
            Ta[(r0 + r) * ST + j] = acc[r] + Tb[(r0 + r) * ST + j];
    }
    __syncthreads();
    // V = E * Cp -> Tb
    {
        float acc[4] = {0.f, 0.f, 0.f, 0.f};
        mm32(Ta, sCp, acc, r0, j);
        #pragma unroll
        for (int r = 0; r < 4; r++) Tb[(r0 + r) * ST + j] = acc[r];
    }
    __syncthreads();
    // out = Cp * V
    {
        float acc[4] = {0.f, 0.f, 0.f, 0.f};
        mm32(sCp, Tb, acc, r0, j);
        #pragma unroll
        for (int r = 0; r < 4; r++) out[cn * 1024 + (r0 + r) * 32 + j] = acc[r];
    }
}

// ============================================================================
extern "C" void kernel_launch(void* const* d_in, const int* in_sizes, int n_in,
                              void* d_out, int out_size) {
    const float* X = nullptr;
    const float* C = nullptr;
    const int* idx = nullptr;
    int xElems = 0;
    for (int i = 0; i < n_in; i++) {
        if (in_sizes[i] == NB) idx = (const int*)d_in[i];
        else if (in_sizes[i] == NCN * 1024) C = (const float*)d_in[i];
        else { X = (const float*)d_in[i]; xElems = in_sizes[i]; }
    }
    const int batch = xElems / (NCN * 1024);

    if (batch == NBINS) {
        dedup_kernel<<<1, 1024>>>(idx);
    } else {
        nodedup_kernel<<<1, NB>>>(idx);
    }
    dim3 grid(NCHUNK, NCN);
    main_kernel<<<grid, 256>>>(X, C);
    dim3 mgrid(NCN, NMID);
    midreduce_kernel<<<mgrid, 1024>>>();
    final_kernel<<<NCN, 256>>>(C, (float*)d_out);
}

// round 9
// speedup vs baseline: 5.7492x; 1.0600x over previous
#include <cuda_runtime.h>
#include <cstdint>
#include <cstddef>

#define NCN    32      // 2*16 centroid matrices
#define NB     1024    // number of sampled indices
#define NBINS  2048    // batch size B (histogram bins)
#define NCHUNK 128     // b-chunks in main kernel grid
#define WPB    8       // warps per block (main kernel)
#define NMID   8       // mid-reduced chunk count
#define SSUM   3.0f    // sum of w_i/t_i for GL-2 on [0,1] (exactly 3)
#define ST     36      // padded row stride for final-kernel matrices

// polar-express quintic sign coefficients
#define PE_A   3.4445f
#define PE_B  (-4.7750f)
#define PE_C   2.0315f
#define NPE    4       // quintic iterations
#define NNS    5       // Newton-Schulz refinement iterations
#define NSQ    5       // Newton-Schulz sqrt iterations

// ---- scratch (static device globals; no allocation APIs) ----
__device__ float g_partial[NCHUNK * NCN * 1024];      // per-chunk partial sums
__device__ float g_partial2[NMID * NCN * 1024];       // mid-reduced partials
__device__ int   g_list[NB];                          // distinct xb values (ascending)
__device__ float g_cnt[NB];                           // multiplicity weights (0 = idle)

// Gauss-Legendre 2-node on [0,1]
#define T0   0.21132486540518713f
#define T1   0.78867513459481287f
#define WOT0 2.3660254037844384f
#define WOT1 0.6339745962155614f

// ---- packed f32x2 helpers ----
union f2u { float2 f; unsigned long long u; };
__device__ __forceinline__ float2 ffma2(float2 a, float2 b, float2 c) {
    f2u A, B, C, R; A.f = a; B.f = b; C.f = c;
    asm("fma.rn.f32x2 %0, %1, %2, %3;" : "=l"(R.u) : "l"(A.u), "l"(B.u), "l"(C.u));
    return R.f;
}
struct __align__(16) pf4 { float2 lo, hi; };

__device__ __forceinline__ float f4c(const float4 v, int c) {
    return c == 0 ? v.x : c == 1 ? v.y : c == 2 ? v.z : v.w;
}

// ============================================================================
// Dedup in one launch: smem histogram + ordered compaction (deterministic).
// ============================================================================
__global__ void dedup_kernel(const int* __restrict__ idx) {
    __shared__ int h[NBINS];
    __shared__ int s1[1024], s2[1024];
    const int t = threadIdx.x;
    h[t] = 0; h[t + 1024] = 0;
    g_list[t] = 0; g_cnt[t] = 0.f;
    __syncthreads();
    atomicAdd(&h[idx[t]], 1);
    __syncthreads();
    const int h0 = h[2 * t], h1 = h[2 * t + 1];
    const int p0 = h0 > 0, p1 = h1 > 0;
    s1[t] = p0 + p1;
    __syncthreads();
    int* src = s1; int* dst = s2;
    for (int off = 1; off < 1024; off <<= 1) {
        int v = src[t];
        if (t >= off) v += src[t - off];
        dst[t] = v;
        __syncthreads();
        int* tmp = src; src = dst; dst = tmp;
    }
    const int excl = src[t] - (p0 + p1);
    if (p0) { g_list[excl] = 2 * t;          g_cnt[excl] = (float)h0; }
    if (p1) { g_list[excl + p0] = 2 * t + 1; g_cnt[excl + p0] = (float)h1; }
}
__global__ void nodedup_kernel(const int* __restrict__ idx) {
    g_list[threadIdx.x] = idx[threadIdx.x];
    g_cnt[threadIdx.x] = 1.f;
}

// ============================================================================
// Main kernel: accumulate w*(wot0*inv(B0)+wot1*inv(B1)), B_nd = t_nd*X+(1-t_nd)*C.
// One warp per (slot, cn). Block-pivot (4x4) pivot-free Gauss-Jordan:
// 8 rounds/inverse; per-round the lane solves F = cd * P^{-1} via an in-register
// no-pivot LU of P^T (P is SPD: diagonal block of a Schur complement), then a
// rank-4 packed-FMA update against the broadcast panel.
// ============================================================================
__global__ void __launch_bounds__(256, 3) main_kernel(const float* __restrict__ X,
                                                      const float* __restrict__ Cin) {
    __shared__ __align__(16) float sC[32 * 36];         // C rows (stride 36)
    __shared__ __align__(16) float sBuf[WPB][32 * 36];  // per-warp accumulator
    __shared__ __align__(16) float sBc[WPB][2][4 * 36]; // dbl-buffered 4-row panel
    const int tid = threadIdx.x, warp = tid >> 5, lane = tid & 31;
    const int cn = blockIdx.y;
    const int slot = blockIdx.x * WPB + warp;

    for (int k = tid; k < 1024; k += 256)
        sC[(k >> 5) * 36 + (k & 31)] = Cin[cn * 1024 + k];
    __syncthreads();

    float* bufrow = sBuf[warp] + lane * 36;
    pf4* br = (pf4*)bufrow;
    const float w = g_cnt[slot];

    if (w > 0.f) {
        const float* Xrow = X + (((size_t)g_list[slot] * NCN + cn) << 10) + (lane << 5);
        const pf4* crow = (const pf4*)(sC + lane * 36);
        const int myblk = lane >> 2, myr = lane & 3;

        #pragma unroll 1
        for (int nd = 0; nd < 2; nd++) {
            const float t = nd ? T1 : T0;
            const float omt = 1.f - t;
            const float2 t2 = make_float2(t, t);

            // B = t*X + (1-t)*C   (row `lane` in registers)
            float2 B2[16];
            #pragma unroll
            for (int q = 0; q < 8; q++) {
                const float4 xv = ((const float4*)Xrow)[q];
                const pf4 cv = crow[q];
                B2[2*q]   = ffma2(t2, make_float2(xv.x, xv.y),
                                  make_float2(omt * cv.lo.x, omt * cv.lo.y));
                B2[2*q+1] = ffma2(t2, make_float2(xv.z, xv.w),
                                  make_float2(omt * cv.hi.x, omt * cv.hi.y));
            }

            // block-pivot Gauss-Jordan inverse (8 rounds of 4 columns)
            #pragma unroll
            for (int kb = 0; kb < 8; kb++) {
                float* bc = sBc[warp][kb & 1];
                if (myblk == kb) {
                    pf4* bp = (pf4*)(bc + myr * 36);
                    #pragma unroll
                    for (int q = 0; q < 8; q++) {
                        pf4 v; v.lo = B2[2*q]; v.hi = B2[2*q+1];
                        bp[q] = v;
                    }
                }
                __syncwarp();
                // pivot block P (rows 0..3 of panel, cols 4kb..4kb+3)
                const float4 p0 = *(const float4*)(bc +   0 + 4 * kb);
                const float4 p1 = *(const float4*)(bc +  36 + 4 * kb);
                const float4 p2 = *(const float4*)(bc +  72 + 4 * kb);
                const float4 p3 = *(const float4*)(bc + 108 + 4 * kb);

                // own block-column values minus identity (unified owner trick)
                const float cd0 = B2[2*kb].x   - ((lane == 4*kb + 0) ? 1.f : 0.f);
                const float cd1 = B2[2*kb].y   - ((lane == 4*kb + 1) ? 1.f : 0.f);
                const float cd2 = B2[2*kb+1].x - ((lane == 4*kb + 2) ? 1.f : 0.f);
                const float cd3 = B2[2*kb+1].y - ((lane == 4*kb + 3) ? 1.f : 0.f);

                // Solve F * P = cd  <=>  P^T F^T = cd^T. LU of M = P^T
                // (no pivoting: P is SPD). M[i][j] = P(j,i).
                float m01 = p1.x, m02 = p2.x, m03 = p3.x;
                float m11 = p1.y, m12 = p2.y, m13 = p3.y;
                float m21 = p1.z, m22 = p2.z, m23 = p3.z;
                float m31 = p1.w, m32 = p2.w, m33 = p3.w;
                const float i00 = __fdividef(1.f, p0.x);
                const float l10 = p0.y * i00, l20 = p0.z * i00, l30 = p0.w * i00;
                m11 = fmaf(-l10, m01, m11); m12 = fmaf(-l10, m02, m12); m13 = fmaf(-l10, m03, m13);
                m21 = fmaf(-l20, m01, m21); m22 = fmaf(-l20, m02, m22); m23 = fmaf(-l20, m03, m23);
                m31 = fmaf(-l30, m01, m31); m32 = fmaf(-l30, m02, m32); m33 = fmaf(-l30, m03, m33);
                const float i11 = __fdividef(1.f, m11);
                const float l21 = m21 * i11, l31 = m31 * i11;
                m22 = fmaf(-l21, m12, m22); m23 = fmaf(-l21, m13, m23);
                m32 = fmaf(-l31, m12, m32); m33 = fmaf(-l31, m13, m33);
                const float i22 = __fdividef(1.f, m22);
                const float l32 = m32 * i22;
                m33 = fmaf(-l32, m23, m33);
                const float i33 = __fdividef(1.f, m33);
                // forward substitution (unit lower)
                const float y0 = cd0;
                const float y1 = fmaf(-l10, y0, cd1);
                const float y2 = fmaf(-l21, y1, fmaf(-l20, y0, cd2));
                const float y3 = fmaf(-l32, y2, fmaf(-l31, y1, fmaf(-l30, y0, cd3)));
                // back substitution
                const float F3 = y3 * i33;
                const float F2 = fmaf(-m23, F3, y2) * i22;
                const float F1 = fmaf(-m13, F3, fmaf(-m12, F2, y1)) * i11;
                const float F0 = fmaf(-m03, F3, fmaf(-m02, F2, fmaf(-m01, F1, y0))) * i00;

                const float2 nF0 = make_float2(-F0, -F0), nF1 = make_float2(-F1, -F1);
                const float2 nF2 = make_float2(-F2, -F2), nF3 = make_float2(-F3, -F3);
                const pf4* r0 = (const pf4*)(bc);
                const pf4* r1 = (const pf4*)(bc + 36);
                const pf4* r2 = (const pf4*)(bc + 72);
                const pf4* r3 = (const pf4*)(bc + 108);
                #pragma unroll
                for (int q = 0; q < 8; q++) {
                    const pf4 v0 = r0[q], v1 = r1[q], v2 = r2[q], v3 = r3[q];
                    B2[2*q]   = ffma2(nF0, v0.lo, ffma2(nF1, v1.lo,
                                ffma2(nF2, v2.lo, ffma2(nF3, v3.lo, B2[2*q]))));
                    B2[2*q+1] = ffma2(nF0, v0.hi, ffma2(nF1, v1.hi,
                                ffma2(nF2, v2.hi, ffma2(nF3, v3.hi, B2[2*q+1]))));
                }
                // block-column fixup: delta - F
                B2[2*kb]   = make_float2(((lane == 4*kb + 0) ? 1.f : 0.f) - F0,
                                         ((lane == 4*kb + 1) ? 1.f : 0.f) - F1);
                B2[2*kb+1] = make_float2(((lane == 4*kb + 2) ? 1.f : 0.f) - F2,
                                         ((lane == 4*kb + 3) ? 1.f : 0.f) - F3);
            }

            // accumulate (w*wot)*Binv into own sBuf row
            const float sw = w * (nd ? WOT1 : WOT0);
            const float2 sw2 = make_float2(sw, sw);
            if (nd == 0) {
                #pragma unroll
                for (int q = 0; q < 8; q++) {
                    pf4 v;
                    v.lo = make_float2(sw * B2[2*q].x, sw * B2[2*q].y);
                    v.hi = make_float2(sw * B2[2*q+1].x, sw * B2[2*q+1].y);
                    br[q] = v;
                }
            } else {
                #pragma unroll
                for (int q = 0; q < 8; q++) {
                    pf4 v = br[q];
                    v.lo = ffma2(sw2, B2[2*q], v.lo);
                    v.hi = ffma2(sw2, B2[2*q+1], v.hi);
                    br[q] = v;
                }
            }
        }
    } else {
        pf4 z; z.lo = make_float2(0.f, 0.f); z.hi = z.lo;
        #pragma unroll
        for (int q = 0; q < 8; q++) br[q] = z;
    }
    __syncthreads();

    // deterministic block reduction over the 8 warps -> partial buffer
    float* outp = g_partial + ((size_t)blockIdx.x * NCN + cn) * 1024;
    for (int e = tid; e < 1024; e += 256) {
        const int r = e >> 5, cc = e & 31;
        float s = 0.f;
        #pragma unroll
        for (int wp = 0; wp < WPB; wp++) s += sBuf[wp][r * 36 + cc];
        outp[e] = s;
    }
}

// ============================================================================
// Mid-reduction: collapse 128 chunks -> 8, at full-chip DRAM bandwidth.
// ============================================================================
__global__ void midreduce_kernel() {
    const int cn = blockIdx.x, g = blockIdx.y, tid = threadIdx.x;
    float s = 0.f;
    const float* pp = g_partial + ((size_t)(g * (NCHUNK / NMID)) * NCN + cn) * 1024 + tid;
    #pragma unroll
    for (int c = 0; c < NCHUNK / NMID; c++) s += pp[(size_t)c * NCN * 1024];
    g_partial2[((size_t)g * NCN + cn) * 1024 + tid] = s;
}

// ============================================================================
// Final kernel: 256 threads, register-tiled matmul passes (warp w owns rows
// 4w..4w+3, lane = column). One __syncthreads per pass.
//   Cp = sqrtm(C) (NS); L = eta*(SSUM*I - Cp*Abar*Cp)
//   S = sgn(L) via 4x quintic polar-express + 5x NS refine
//   E = S*cosh(L) + sinh(L);  out = Cp * E * Cp
// ============================================================================

// acc[r] += A(r0+r, :) * B(:, j)   A rows via LDS.128 broadcast, B cols scalar
__device__ __forceinline__ void mm32(const float* __restrict__ A,
                                     const float* __restrict__ B,
                                     float* acc, int r0, int j) {
    #pragma unroll
    for (int kb = 0; kb < 8; kb++) {
        const float4 a0 = *(const float4*)(A + (r0+0)*ST + 4*kb);
        const float4 a1 = *(const float4*)(A + (r0+1)*ST + 4*kb);
        const float4 a2 = *(const float4*)(A + (r0+2)*ST + 4*kb);
        const float4 a3 = *(const float4*)(A + (r0+3)*ST + 4*kb);
        #pragma unroll
        for (int t = 0; t < 4; t++) {
            const float bk = B[(4*kb + t)*ST + j];
            acc[0] = fmaf(f4c(a0, t), bk, acc[0]);
            acc[1] = fmaf(f4c(a1, t), bk, acc[1]);
            acc[2] = fmaf(f4c(a2, t), bk, acc[2]);
            acc[3] = fmaf(f4c(a3, t), bk, acc[3]);
        }
    }
}

__global__ void __launch_bounds__(256) final_kernel(const float* __restrict__ C,
                                                    float* __restrict__ out) {
    __shared__ __align__(16) float sCp[32*ST], sL[32*ST];
    __shared__ __align__(16) float b1[32*ST], b2[32*ST], b3[32*ST], b4[32*ST], b5[32*ST];
    __shared__ float sRed[8];
    __shared__ float sScal;
    const int cn = blockIdx.x, tid = threadIdx.x;
    const int warp = tid >> 5, j = tid & 31, r0 = warp << 2;

    // load C rows; trace
    float cv[4];
    #pragma unroll
    for (int r = 0; r < 4; r++) cv[r] = C[cn * 1024 + (r0 + r) * 32 + j];
    {
        float v = 0.f;
        #pragma unroll
        for (int r = 0; r < 4; r++) if (j == r0 + r) v += cv[r];
        #pragma unroll
        for (int o = 16; o > 0; o >>= 1) v += __shfl_xor_sync(0xffffffffu, v, o);
        if (j == 0) sRed[warp] = v;
    }
    __syncthreads();
    if (tid == 0) {
        float s = 0.f;
        #pragma unroll
        for (int r = 0; r < 8; r++) s += sRed[r];
        sScal = s * (1.f / 32.f);
    }
    __syncthreads();
    const float c = sScal, invc = 1.f / c;

    // NS coupled sqrt on C/c: Y in b1, Z in b2
    #pragma unroll
    for (int r = 0; r < 4; r++) {
        b1[(r0 + r) * ST + j] = cv[r] * invc;
        b2[(r0 + r) * ST + j] = (r0 + r == j) ? 1.f : 0.f;
    }
    __syncthreads();
    float *Y = b1, *Z = b2, *Pm = b3, *Ya = b4, *Za = b5;
    for (int it = 0; it < NSQ; it++) {
        float acc[4] = {0.f, 0.f, 0.f, 0.f};
        mm32(Z, Y, acc, r0, j);
        #pragma unroll
        for (int r = 0; r < 4; r++)
            Pm[(r0 + r) * ST + j] = ((r0 + r == j) ? 1.5f : 0.f) - 0.5f * acc[r];
        __syncthreads();
        float a1[4] = {0.f, 0.f, 0.f, 0.f}, a2[4] = {0.f, 0.f, 0.f, 0.f};
        mm32(Y, Pm, a1, r0, j);
        mm32(Pm, Z, a2, r0, j);
        #pragma unroll
        for (int r = 0; r < 4; r++) {
            Ya[(r0 + r) * ST + j] = a1[r];
            Za[(r0 + r) * ST + j] = a2[r];
        }
        __syncthreads();
        float* t1 = Y; float* t2 = Z;
        Y = Ya; Z = Za; Ya = t1; Za = t2;
    }
    // Cp = Y * sqrt(c)
    const float sc = sqrtf(c);
    #pragma unroll
    for (int r = 0; r < 4; r++) sCp[(r0 + r) * ST + j] = Y[(r0 + r) * ST + j] * sc;
    __syncthreads();
    // all of b1..b5 now scratch
    float *S = b1, *Sn = b2, *Ta = b3, *Tb = b4, *Tc = b5;

    // Abar -> Ta
    #pragma unroll
    for (int r = 0; r < 4; r++) {
        float s = 0.f;
        #pragma unroll
        for (int g = 0; g < NMID; g++)
            s += g_partial2[((size_t)g * NCN + cn) * 1024 + (r0 + r) * 32 + j];
        Ta[(r0 + r) * ST + j] = s * (1.f / 1024.f);
    }
    __syncthreads();
    // U = Abar * Cp -> Tb
    {
        float acc[4] = {0.f, 0.f, 0.f, 0.f};
        mm32(Ta, sCp, acc, r0, j);
        #pragma unroll
        for (int r = 0; r < 4; r++) Tb[(r0 + r) * ST + j] = acc[r];
    }
    __syncthreads();
    // L = eta*(SSUM*I - Cp*U) -> sL ; Frobenius norm
    {
        float acc[4] = {0.f, 0.f, 0.f, 0.f};
        mm32(sCp, Tb, acc, r0, j);
        float fr = 0.f;
        #pragma unroll
        for (int r = 0; r < 4; r++) {
            const float lv = 0.01f * (((r0 + r == j) ? SSUM : 0.f) - acc[r]);
            sL[(r0 + r) * ST + j] = lv;
            fr = fmaf(lv, lv, fr);
        }
        #pragma unroll
        for (int o = 16; o > 0; o >>= 1) fr += __shfl_xor_sync(0xffffffffu, fr, o);
        if (j == 0) sRed[warp] = fr;
    }
    __syncthreads();
    if (tid == 0) {
        float s = 0.f;
        #pragma unroll
        for (int r = 0; r < 8; r++) s += sRed[r];
        sScal = rsqrtf(s + 1e-30f);
    }
    __syncthreads();
    // S0 = L / ||L||_F
    {
        const float ia = sScal;
        #pragma unroll
        for (int r = 0; r < 4; r++) S[(r0 + r) * ST + j] = sL[(r0 + r) * ST + j] * ia;
    }
    __syncthreads();

    // quintic polar-express iterations: S <- PE_A*S + PE_B*S^3 + PE_C*S^5
    for (int it = 0; it < NPE; it++) {
        float acc[4] = {0.f, 0.f, 0.f, 0.f};
        mm32(S, S, acc, r0, j);                 // T = S^2
        #pragma unroll
        for (int r = 0; r < 4; r++) Ta[(r0 + r) * ST + j] = acc[r];
        __syncthreads();
        float ac2[4] = {0.f, 0.f, 0.f, 0.f};
        mm32(Ta, Ta, ac2, r0, j);               // T2 = T^2
        #pragma unroll
        for (int r = 0; r < 4; r++)
            Tb[(r0 + r) * ST + j] = ((r0 + r == j) ? PE_A : 0.f)
                                  + PE_B * Ta[(r0 + r) * ST + j] + PE_C * ac2[r];
        __syncthreads();
        float ac3[4] = {0.f, 0.f, 0.f, 0.f};
        mm32(S, Tb, ac3, r0, j);                // S' = S * P
        #pragma unroll
        for (int r = 0; r < 4; r++) Sn[(r0 + r) * ST + j] = ac3[r];
        __syncthreads();
        float* t = S; S = Sn; Sn = t;
    }
    // NS refinement: S <- 1.5S - 0.5 S^3
    for (int it = 0; it < NNS; it++) {
        float acc[4] = {0.f, 0.f, 0.f, 0.f};
        mm32(S, S, acc, r0, j);
        #pragma unroll
        for (int r = 0; r < 4; r++) Ta[(r0 + r) * ST + j] = acc[r];
        __syncthreads();
        float ac2[4] = {0.f, 0.f, 0.f, 0.f};
        mm32(S, Ta, ac2, r0, j);
        #pragma unroll
        for (int r = 0; r < 4; r++)
            Sn[(r0 + r) * ST + j] = 1.5f * S[(r0 + r) * ST + j] - 0.5f * ac2[r];
        __syncthreads();
        float* t = S; S = Sn; Sn = t;
    }

    // P2 = L*L -> Ta
    {
        float acc[4] = {0.f, 0.f, 0.f, 0.f};
        mm32(sL, sL, acc, r0, j);
        #pragma unroll
        for (int r = 0; r < 4; r++) Ta[(r0 + r) * ST + j] = acc[r];
    }
    __syncthreads();
    // sinh(L) ~= L + L*P2/6 -> Tb
    {
        float acc[4] = {0.f, 0.f, 0.f, 0.f};
        mm32(sL, Ta, acc, r0, j);
        #pragma unroll
        for (int r = 0; r < 4; r++)
            Tb[(r0 + r) * ST + j] = fmaf(acc[r], (1.f / 6.f), sL[(r0 + r) * ST + j]);
    }
    __syncthreads();
    // cosh(L) ~= I + P2/2 + P2*P2/24 -> Tc
    {
        float acc[4] = {0.f, 0.f, 0.f, 0.f};
        mm32(Ta, Ta, acc, r0, j);
        #pragma unroll
        for (int r = 0; r < 4; r++)
            Tc[(r0 + r) * ST + j] = ((r0 + r == j) ? 1.f : 0.f)
                                  + 0.5f * Ta[(r0 + r) * ST + j] + acc[r] * (1.f / 24.f);
    }
    __syncthreads();
    // E = S*cosh + sinh -> Ta
    {
        float acc[4] = {0.f, 0.f, 0.f, 0.f};
        mm32(S, Tc, acc, r0, j);
        #pragma unroll
        for (int r = 0; r < 4; r++)
            Ta[(r0 + r) * ST + j] = acc[r] + Tb[(r0 + r) * ST + j];
    }
    __syncthreads();
    // V = E * Cp -> Tb
    {
        float acc[4] = {0.f, 0.f, 0.f, 0.f};
        mm32(Ta, sCp, acc, r0, j);
        #pragma unroll
        for (int r = 0; r < 4; r++) Tb[(r0 + r) * ST + j] = acc[r];
    }
    __syncthreads();
    // out = Cp * V
    {
        float acc[4] = {0.f, 0.f, 0.f, 0.f};
        mm32(sCp, Tb, acc, r0, j);
        #pragma unroll
        for (int r = 0; r < 4; r++) out[cn * 1024 + (r0 + r) * 32 + j] = acc[r];
    }
}

// ============================================================================
extern "C" void kernel_launch(void* const* d_in, const int* in_sizes, int n_in,
                              void* d_out, int out_size) {
    const float* X = nullptr;
    const float* C = nullptr;
    const int* idx = nullptr;
    int xElems = 0;
    for (int i = 0; i < n_in; i++) {
        if (in_sizes[i] == NB) idx = (const int*)d_in[i];
        else if (in_sizes[i] == NCN * 1024) C = (const float*)d_in[i];
        else { X = (const float*)d_in[i]; xElems = in_sizes[i]; }
    }
    const int batch = xElems / (NCN * 1024);

    if (batch == NBINS) {
        dedup_kernel<<<1, 1024>>>(idx);
    } else {
        nodedup_kernel<<<1, NB>>>(idx);
    }
    dim3 grid(NCHUNK, NCN);
    main_kernel<<<grid, 256>>>(X, C);
    dim3 mgrid(NCN, NMID);
    midreduce_kernel<<<mgrid, 1024>>>();
    final_kernel<<<NCN, 256>>>(C, (float*)d_out);
}